// round 3
// baseline (speedup 1.0000x reference)
#include <cuda_runtime.h>
#include <math.h>
#include <stdint.h>

// ---------------- Problem constants ----------------
#define NSRC0   60000
#define NDST0   30000
#define NE0     480000
#define NDST1   8000
#define NE1     128000
#define IMG_D   1024
#define BLK_D   768
#define FUSED_D 512
#define H1      8
#define O1      64      // FUSED/H1
#define O2      128     // OUT_D

// ---------------- Device scratch (static: no allocations allowed) ----------
__device__ float g_fi[(size_t)NSRC0 * FUSED_D];   // fi, later z1
__device__ float g_ti[(size_t)NSRC0 * FUSED_D];   // ti
__device__ float g_av[(size_t)NSRC0 * FUSED_D];   // alpha_v, later fused
__device__ float g_ae[(size_t)NSRC0 * FUSED_D];   // alpha_e
__device__ float g_h [(size_t)NDST0 * FUSED_D];   // layer1 output (h)
__device__ float g_z2[(size_t)NDST0 * O2];        // layer2 z
__device__ float g_s1s[(size_t)NSRC0 * H1];
__device__ float g_s1d[(size_t)NSRC0 * H1];
__device__ float g_e1 [(size_t)NE0   * H1];
__device__ float g_m1 [(size_t)NDST0 * H1];
__device__ float g_d1 [(size_t)NDST0 * H1];
__device__ float g_s2s[(size_t)NDST0];
__device__ float g_s2d[(size_t)NDST0];
__device__ float g_e2 [(size_t)NE1];
__device__ float g_m2 [(size_t)NDST1];
__device__ float g_d2 [(size_t)NDST1];

// ---------------- Utility kernels ----------------
__global__ void fill_kernel(float* __restrict__ p, float v, int n) {
    int i = blockIdx.x * blockDim.x + threadIdx.x;
    if (i < n) p[i] = v;
}

// fused = sigmoid_av * fi + sigmoid_ae * ti  (av/ae already sigmoided in GEMM epilogue)
__global__ void fuse_kernel(float* __restrict__ av, const float* __restrict__ fi,
                            const float* __restrict__ ae, const float* __restrict__ ti, int n) {
    int i = blockIdx.x * blockDim.x + threadIdx.x;
    if (i < n) av[i] = av[i] * fi[i] + ae[i] * ti[i];
}

__global__ void elu_kernel(float* __restrict__ p, int n) {
    int i = blockIdx.x * blockDim.x + threadIdx.x;
    if (i < n) {
        float x = p[i];
        p[i] = x > 0.f ? x : expm1f(x);
    }
}

// ---------------- SGEMM: C[M,N] = A[M,K] * B  (+bias, optional sigmoid) -----
// TRANSB=1: B is [N,K] row-major (weight [out,in], x @ W^T)
// TRANSB=0: B is [K,N] row-major
template<int TRANSB>
__global__ void __launch_bounds__(256, 2) sgemm_kernel(
    const float* __restrict__ A, const float* __restrict__ B, float* __restrict__ C,
    int M, int N, int K, const float* __restrict__ bias, int act)
{
    const int BM = 128, BN = 128, BK = 16;
    __shared__ float As[BK][BM];
    __shared__ float Bs[BK][BN];

    int bm = blockIdx.y * BM;
    int bn = blockIdx.x * BN;
    int tid = threadIdx.x;
    int tr = tid / 16;           // 0..15 (row group)
    int tc = tid % 16;           // 0..15 (col group)

    float acc[8][8];
    #pragma unroll
    for (int i = 0; i < 8; i++)
        #pragma unroll
        for (int j = 0; j < 8; j++) acc[i][j] = 0.f;

    for (int k0 = 0; k0 < K; k0 += BK) {
        // Load A tile (BM x BK)
        #pragma unroll
        for (int i = tid; i < BM * BK; i += 256) {
            int r = i / BK, c = i % BK;
            int gm = bm + r;
            As[c][r] = (gm < M) ? A[(size_t)gm * K + k0 + c] : 0.f;
        }
        // Load B tile (BK x BN)
        if (TRANSB) {
            #pragma unroll
            for (int i = tid; i < BN * BK; i += 256) {
                int r = i / BK, c = i % BK;   // r = n, c = k
                int gn = bn + r;
                Bs[c][r] = (gn < N) ? B[(size_t)gn * K + k0 + c] : 0.f;
            }
        } else {
            #pragma unroll
            for (int i = tid; i < BN * BK; i += 256) {
                int r = i / BN, c = i % BN;   // r = k, c = n
                int gn = bn + c;
                Bs[r][c] = (gn < N) ? B[(size_t)(k0 + r) * N + gn] : 0.f;
            }
        }
        __syncthreads();

        #pragma unroll
        for (int kk = 0; kk < BK; kk++) {
            float a[8], b[8];
            #pragma unroll
            for (int i = 0; i < 8; i++) a[i] = As[kk][tr * 8 + i];
            #pragma unroll
            for (int j = 0; j < 8; j++) b[j] = Bs[kk][tc * 8 + j];
            #pragma unroll
            for (int i = 0; i < 8; i++)
                #pragma unroll
                for (int j = 0; j < 8; j++)
                    acc[i][j] = fmaf(a[i], b[j], acc[i][j]);
        }
        __syncthreads();
    }

    #pragma unroll
    for (int i = 0; i < 8; i++) {
        int gm = bm + tr * 8 + i;
        if (gm >= M) continue;
        #pragma unroll
        for (int j = 0; j < 8; j++) {
            int gn = bn + tc * 8 + j;
            if (gn >= N) continue;
            float v = acc[i][j];
            if (bias) v += bias[gn];
            if (act)  v = 1.f / (1.f + expf(-v));
            C[(size_t)gm * N + gn] = v;
        }
    }
}

// ---------------- GAT attention-score kernel ----------------
// z: [Nn, H*O]  a: [H, 2O]   s_src[n,h] = sum_o z*a[h,o],  s_dst uses a[h,O+o]
__global__ void scores_kernel(const float* __restrict__ z, const float* __restrict__ a,
                              float* __restrict__ ssrc, float* __restrict__ sdst,
                              int Nn, int H, int O)
{
    int idx = blockIdx.x * blockDim.x + threadIdx.x;
    if (idx >= Nn * H) return;
    int n = idx / H, h = idx % H;
    const float* zp = z + ((size_t)n * H + h) * O;
    const float* as = a + (size_t)h * 2 * O;
    const float* ad = as + O;
    float s1 = 0.f, s2 = 0.f;
    for (int o = 0; o < O; o++) {
        float zv = zp[o];
        s1 = fmaf(zv, as[o], s1);
        s2 = fmaf(zv, ad[o], s2);
    }
    ssrc[idx] = s1;
    sdst[idx] = s2;
}

// ---------------- Edge softmax kernels ----------------
__device__ __forceinline__ void atomicMaxF(float* addr, float val) {
    if (val >= 0.f) atomicMax((int*)addr, __float_as_int(val));
    else            atomicMin((unsigned int*)addr, __float_as_uint(val));
}

__global__ void edge_logits_kernel(const float* __restrict__ ssrc, const float* __restrict__ sdst,
                                   const int* __restrict__ src, const int* __restrict__ dst,
                                   float* __restrict__ ebuf, float* __restrict__ mbuf,
                                   int E, int H)
{
    int idx = blockIdx.x * blockDim.x + threadIdx.x;
    if (idx >= E * H) return;
    int e = idx / H, h = idx % H;
    int s = src[e], d = dst[e];
    float v = ssrc[(size_t)s * H + h] + sdst[(size_t)d * H + h];
    v = v > 0.f ? v : 0.01f * v;   // leaky_relu(0.01)
    ebuf[idx] = v;
    atomicMaxF(&mbuf[(size_t)d * H + h], v);
}

__global__ void edge_exp_kernel(float* __restrict__ ebuf,
                                const int* __restrict__ dst,
                                const float* __restrict__ mbuf, float* __restrict__ den,
                                int E, int H)
{
    int idx = blockIdx.x * blockDim.x + threadIdx.x;
    if (idx >= E * H) return;
    int e = idx / H, h = idx % H;
    int d = dst[e];
    float v = expf(ebuf[idx] - mbuf[(size_t)d * H + h]);
    ebuf[idx] = v;
    atomicAdd(&den[(size_t)d * H + h], v);
}

// one thread per (edge, head, 4-wide output chunk)
__global__ void edge_agg_kernel(const float* __restrict__ ex, const float* __restrict__ den,
                                const int* __restrict__ src, const int* __restrict__ dst,
                                const float* __restrict__ z, float* __restrict__ out,
                                int E, int H, int O)
{
    int idx = blockIdx.x * blockDim.x + threadIdx.x;
    int groups = O / 4;
    int per_edge = H * groups;
    if (idx >= E * per_edge) return;
    int e = idx / per_edge;
    int r = idx % per_edge;
    int h = r / groups;
    int q = r % groups;
    int s = src[e], d = dst[e];
    float coef = ex[(size_t)e * H + h] / den[(size_t)d * H + h];
    const float4 zv = *reinterpret_cast<const float4*>(z + ((size_t)s * H + h) * O + q * 4);
    float* po = out + ((size_t)d * H + h) * O + q * 4;
    atomicAdd(po + 0, coef * zv.x);
    atomicAdd(po + 1, coef * zv.y);
    atomicAdd(po + 2, coef * zv.z);
    atomicAdd(po + 3, coef * zv.w);
}

// ---------------- Host orchestration ----------------
static inline int cdiv(int a, int b) { return (a + b - 1) / b; }

extern "C" void kernel_launch(void* const* d_in, const int* in_sizes, int n_in,
                              void* d_out, int out_size)
{
    const float* img   = (const float*)d_in[0];
    const float* blk   = (const float*)d_in[1];
    const float* W_img = (const float*)d_in[2];
    const float* W_blk = (const float*)d_in[3];
    const float* Wv    = (const float*)d_in[4];
    const float* bv    = (const float*)d_in[5];
    const float* We    = (const float*)d_in[6];
    const float* be    = (const float*)d_in[7];
    const float* fc1   = (const float*)d_in[8];   // [8,64,512] -> flat [512,512]
    const float* attn1 = (const float*)d_in[9];   // [8,128]
    const float* fc2   = (const float*)d_in[10];  // [1,128,512] -> [128,512]
    const float* attn2 = (const float*)d_in[11];  // [1,256]
    const int* e0s = (const int*)d_in[12];
    const int* e0d = (const int*)d_in[13];
    const int* e1s = (const int*)d_in[14];
    const int* e1d = (const int*)d_in[15];
    float* out = (float*)d_out;

    int E0 = in_sizes[12];
    int E1 = in_sizes[14];

    float *fi, *ti, *av, *ae, *hbuf, *z2;
    float *s1s, *s1d, *e1b, *m1, *d1, *s2s, *s2d, *e2b, *m2, *d2;
    cudaGetSymbolAddress((void**)&fi,  g_fi);
    cudaGetSymbolAddress((void**)&ti,  g_ti);
    cudaGetSymbolAddress((void**)&av,  g_av);
    cudaGetSymbolAddress((void**)&ae,  g_ae);
    cudaGetSymbolAddress((void**)&hbuf,g_h);
    cudaGetSymbolAddress((void**)&z2,  g_z2);
    cudaGetSymbolAddress((void**)&s1s, g_s1s);
    cudaGetSymbolAddress((void**)&s1d, g_s1d);
    cudaGetSymbolAddress((void**)&e1b, g_e1);
    cudaGetSymbolAddress((void**)&m1,  g_m1);
    cudaGetSymbolAddress((void**)&d1,  g_d1);
    cudaGetSymbolAddress((void**)&s2s, g_s2s);
    cudaGetSymbolAddress((void**)&s2d, g_s2d);
    cudaGetSymbolAddress((void**)&e2b, g_e2);
    cudaGetSymbolAddress((void**)&m2,  g_m2);
    cudaGetSymbolAddress((void**)&d2,  g_d2);

    const float NEG_INF = -INFINITY;

    // --- init accumulators / outputs ---
    {
        int n;
        n = NDST0 * FUSED_D; fill_kernel<<<cdiv(n,256),256>>>(hbuf, 0.f, n);
        n = NDST1 * O2;      fill_kernel<<<cdiv(n,256),256>>>(out,  0.f, n);
        n = NDST0 * H1;      fill_kernel<<<cdiv(n,256),256>>>(m1, NEG_INF, n);
        n = NDST0 * H1;      fill_kernel<<<cdiv(n,256),256>>>(d1, 0.f, n);
        n = NDST1;           fill_kernel<<<cdiv(n,256),256>>>(m2, NEG_INF, n);
        n = NDST1;           fill_kernel<<<cdiv(n,256),256>>>(d2, 0.f, n);
    }

    dim3 blk256(256);

    // --- CrossAttentionLayer ---
    // fi = img @ W_img^T   [60000,512]
    {
        dim3 grid(cdiv(FUSED_D,128), cdiv(NSRC0,128));
        sgemm_kernel<1><<<grid, blk256>>>(img, W_img, fi, NSRC0, FUSED_D, IMG_D, nullptr, 0);
    }
    // ti = blk @ W_blk^T
    {
        dim3 grid(cdiv(FUSED_D,128), cdiv(NSRC0,128));
        sgemm_kernel<1><<<grid, blk256>>>(blk, W_blk, ti, NSRC0, FUSED_D, BLK_D, nullptr, 0);
    }
    // av = sigmoid(fi @ Wv + bv)   (Wv is [K,N] layout -> TRANSB=0)
    {
        dim3 grid(cdiv(FUSED_D,128), cdiv(NSRC0,128));
        sgemm_kernel<0><<<grid, blk256>>>(fi, Wv, av, NSRC0, FUSED_D, FUSED_D, bv, 1);
    }
    // ae = sigmoid(ti @ We + be)
    {
        dim3 grid(cdiv(FUSED_D,128), cdiv(NSRC0,128));
        sgemm_kernel<0><<<grid, blk256>>>(ti, We, ae, NSRC0, FUSED_D, FUSED_D, be, 1);
    }
    // fused = av*fi + ae*ti   (into av)
    {
        int n = NSRC0 * FUSED_D;
        fuse_kernel<<<cdiv(n,256),256>>>(av, fi, ae, ti, n);
    }

    // --- Layer 1: 8-head GAT ---
    // z1 = fused @ fc1_flat^T   -> into fi (dead)
    {
        dim3 grid(cdiv(FUSED_D,128), cdiv(NSRC0,128));
        sgemm_kernel<1><<<grid, blk256>>>(av, fc1, fi, NSRC0, FUSED_D, FUSED_D, nullptr, 0);
    }
    // attention scores
    {
        int n = NSRC0 * H1;
        scores_kernel<<<cdiv(n,256),256>>>(fi, attn1, s1s, s1d, NSRC0, H1, O1);
    }
    // edge softmax + aggregate
    {
        int n = E0 * H1;
        edge_logits_kernel<<<cdiv(n,256),256>>>(s1s, s1d, e0s, e0d, e1b, m1, E0, H1);
        edge_exp_kernel<<<cdiv(n,256),256>>>(e1b, e0d, m1, d1, E0, H1);
        int na = E0 * H1 * (O1/4);
        edge_agg_kernel<<<cdiv(na,256),256>>>(e1b, d1, e0s, e0d, fi, hbuf, E0, H1, O1);
    }
    // ELU
    {
        int n = NDST0 * FUSED_D;
        elu_kernel<<<cdiv(n,256),256>>>(hbuf, n);
    }

    // --- Layer 2: 1-head GAT (O=128) ---
    // z2 = h @ fc2^T   [30000,128]
    {
        dim3 grid(cdiv(O2,128), cdiv(NDST0,128));
        sgemm_kernel<1><<<grid, blk256>>>(hbuf, fc2, z2, NDST0, O2, FUSED_D, nullptr, 0);
    }
    {
        int n = NDST0 * 1;
        scores_kernel<<<cdiv(n,256),256>>>(z2, attn2, s2s, s2d, NDST0, 1, O2);
    }
    {
        int n = E1;
        edge_logits_kernel<<<cdiv(n,256),256>>>(s2s, s2d, e1s, e1d, e2b, m2, E1, 1);
        edge_exp_kernel<<<cdiv(n,256),256>>>(e2b, e1d, m2, d2, E1, 1);
        int na = E1 * 1 * (O2/4);
        edge_agg_kernel<<<cdiv(na,256),256>>>(e2b, d2, e1s, e1d, z2, out, E1, 1, O2);
    }

    (void)n_in; (void)out_size; (void)in_sizes;
}

// round 7
// speedup vs baseline: 2.2782x; 2.2782x over previous
#include <cuda_runtime.h>
#include <cuda_bf16.h>
#include <math.h>
#include <stdint.h>

// ---------------- Problem constants ----------------
#define NSRC0   60000
#define NDST0   30000
#define NE0     480000
#define NDST1   8000
#define NE1     128000
#define IMG_D   1024
#define BLK_D   768
#define FUSED_D 512
#define H1      8
#define O1      64
#define O2      128

// ---------------- fp32 scratch ----------------
__device__ float g_fi[(size_t)NSRC0 * FUSED_D];   // fi, later z1
__device__ float g_ti[(size_t)NSRC0 * FUSED_D];
__device__ float g_av[(size_t)NSRC0 * FUSED_D];
__device__ float g_ae[(size_t)NSRC0 * FUSED_D];
__device__ float g_h [(size_t)NDST0 * FUSED_D];
__device__ float g_z2[(size_t)NDST0 * O2];
__device__ float g_s1s[(size_t)NSRC0 * H1];
__device__ float g_s1d[(size_t)NSRC0 * H1];
__device__ float g_e1 [(size_t)NE0   * H1];
__device__ float g_m1 [(size_t)NDST0 * H1];
__device__ float g_d1 [(size_t)NDST0 * H1];
__device__ float g_s2s[(size_t)NDST0];
__device__ float g_s2d[(size_t)NDST0];
__device__ float g_e2 [(size_t)NE1];
__device__ float g_m2 [(size_t)NDST1];
__device__ float g_d2 [(size_t)NDST1];

// ---------------- bf16 split-triplet scratch ----------------
__device__ __nv_bfloat16 g_img3[(size_t)NSRC0 * 3 * IMG_D];
__device__ __nv_bfloat16 g_blk3[(size_t)NSRC0 * 3 * BLK_D];
__device__ __nv_bfloat16 g_fi3 [(size_t)NSRC0 * 3 * FUSED_D];
__device__ __nv_bfloat16 g_ti3 [(size_t)NSRC0 * 3 * FUSED_D];
__device__ __nv_bfloat16 g_fu3 [(size_t)NSRC0 * 3 * FUSED_D];
__device__ __nv_bfloat16 g_h3  [(size_t)NDST0 * 3 * FUSED_D];
__device__ __nv_bfloat16 g_wimg3[512 * 3 * IMG_D];
__device__ __nv_bfloat16 g_wblk3[512 * 3 * BLK_D];
__device__ __nv_bfloat16 g_wv3  [512 * 3 * FUSED_D];
__device__ __nv_bfloat16 g_we3  [512 * 3 * FUSED_D];
__device__ __nv_bfloat16 g_fc13 [512 * 3 * FUSED_D];
__device__ __nv_bfloat16 g_fc23 [128 * 3 * FUSED_D];

// ================= PTX helpers (family-profile-safe only) =================
__device__ __forceinline__ uint32_t smem_u32(const void* p) {
    return (uint32_t)__cvta_generic_to_shared(p);
}

__device__ __forceinline__ void cp_async16(uint32_t dst, const void* src, int sz) {
    asm volatile("cp.async.cg.shared.global [%0], [%1], 16, %2;"
                 :: "r"(dst), "l"(src), "r"(sz));
}
#define CP_COMMIT() asm volatile("cp.async.commit_group;" ::: "memory")

__device__ __forceinline__ void ldsm4(uint32_t* r, uint32_t addr) {
    asm volatile("ldmatrix.sync.aligned.m8n8.x4.shared.b16 {%0,%1,%2,%3}, [%4];"
                 : "=r"(r[0]), "=r"(r[1]), "=r"(r[2]), "=r"(r[3]) : "r"(addr));
}

__device__ __forceinline__ void mma_bf16(float* c, const uint32_t* a, const uint32_t* b) {
    asm volatile(
        "mma.sync.aligned.m16n8k16.row.col.f32.bf16.bf16.f32 "
        "{%0,%1,%2,%3}, {%4,%5,%6,%7}, {%8,%9}, {%0,%1,%2,%3};"
        : "+f"(c[0]), "+f"(c[1]), "+f"(c[2]), "+f"(c[3])
        : "r"(a[0]), "r"(a[1]), "r"(a[2]), "r"(a[3]), "r"(b[0]), "r"(b[1]));
}

// ================= bf16 HMMA GEMM =================
// C[M,Nfull] = A[M,K] * B[Nfull,K]^T  (bf16 K-major rows), fp32 accumulate.
// Tile 128x128xBK32, 3-stage cp.async pipeline, 8 warps @ 64x32 each.
#define BMT 128
#define BNT 128
#define BKT 32
#define STAGES 3
#define ROWB 80                 // 32 halves + 8 pad halves = 80 bytes/row
#define STAGE_BYTES ((BMT + BNT) * ROWB)   // 20480

__global__ void __launch_bounds__(256)
gemm_bf16_kernel(const __nv_bfloat16* __restrict__ A,
                 const __nv_bfloat16* __restrict__ B,
                 float* __restrict__ C,
                 const float* __restrict__ bias, int act,
                 __nv_bfloat16* __restrict__ split,
                 int M, int Nfull, int K)
{
    extern __shared__ char smem[];
    const int tid = threadIdx.x;
    const int lane = tid & 31, wid = tid >> 5;
    const int bm = blockIdx.y * BMT;
    const int bn = blockIdx.x * BNT;
    const int wm = (wid >> 2) * 64;      // 2 warp-rows
    const int wn = (wid & 3) * 32;       // 4 warp-cols
    const int T = K / BKT;
    const uint32_t sb = smem_u32(smem);

    float acc[4][4][4];
    #pragma unroll
    for (int i = 0; i < 4; i++)
        #pragma unroll
        for (int j = 0; j < 4; j++)
            #pragma unroll
            for (int k = 0; k < 4; k++) acc[i][j][k] = 0.f;

    // ---- stage loader: A rows then B rows, 16B chunks ----
    auto load_stage = [&](int t, int s) {
        uint32_t base = sb + (uint32_t)s * STAGE_BYTES;
        const __nv_bfloat16* Ab = A + (size_t)bm * K + (size_t)t * BKT;
        const __nv_bfloat16* Bb = B + (size_t)bn * K + (size_t)t * BKT;
        #pragma unroll
        for (int i = tid; i < 1024; i += 256) {
            int row = (i >> 2) & 127;
            int ch  = i & 3;
            if (i < 512) {
                int ok = (bm + row < M);
                const __nv_bfloat16* src = Ab + (size_t)(ok ? row : 0) * K + ch * 8;
                cp_async16(base + row * ROWB + ch * 16, src, ok ? 16 : 0);
            } else {
                cp_async16(base + (BMT + row) * ROWB + ch * 16,
                           Bb + (size_t)row * K + ch * 8, 16);
            }
        }
        CP_COMMIT();
    };

    // prologue
    #pragma unroll
    for (int s = 0; s < STAGES; s++) load_stage(s, s);

    for (int t = 0; t < T; t++) {
        asm volatile("cp.async.wait_group %0;" :: "n"(STAGES - 1));
        __syncthreads();
        uint32_t Abase = sb + (uint32_t)(t % STAGES) * STAGE_BYTES;
        uint32_t Bbase = Abase + BMT * ROWB;
        const int rsel = lane & 15;

        #pragma unroll
        for (int ks = 0; ks < 2; ks++) {
            uint32_t koff = (uint32_t)(ks * 32 + (lane >> 4) * 16);
            uint32_t a[4][4], b[4][2];
            #pragma unroll
            for (int mi = 0; mi < 4; mi++)
                ldsm4(a[mi], Abase + (uint32_t)(wm + 16 * mi + rsel) * ROWB + koff);
            #pragma unroll
            for (int bj = 0; bj < 2; bj++) {
                uint32_t r[4];
                ldsm4(r, Bbase + (uint32_t)(wn + 16 * bj + rsel) * ROWB + koff);
                b[2*bj][0] = r[0]; b[2*bj][1] = r[2];
                b[2*bj+1][0] = r[1]; b[2*bj+1][1] = r[3];
            }
            #pragma unroll
            for (int mi = 0; mi < 4; mi++)
                #pragma unroll
                for (int nj = 0; nj < 4; nj++)
                    mma_bf16(acc[mi][nj], a[mi], b[nj]);
        }
        __syncthreads();
        if (t + STAGES < T) load_stage(t + STAGES, t % STAGES);
        else CP_COMMIT();   // empty group keeps wait_group counting uniform
    }

    // ---- epilogue: bias / sigmoid / fp32 store / optional bf16 split store ----
    #pragma unroll
    for (int mi = 0; mi < 4; mi++) {
        #pragma unroll
        for (int half = 0; half < 2; half++) {
            int gm = bm + wm + 16 * mi + (lane >> 2) + 8 * half;
            if (gm >= M) continue;
            float* crow = C + (size_t)gm * Nfull;
            #pragma unroll
            for (int nj = 0; nj < 4; nj++) {
                int gn = bn + wn + 8 * nj + 2 * (lane & 3);
                float v0 = acc[mi][nj][2 * half + 0];
                float v1 = acc[mi][nj][2 * half + 1];
                if (bias) { v0 += bias[gn]; v1 += bias[gn + 1]; }
                if (act) {
                    v0 = 1.f / (1.f + __expf(-v0));
                    v1 = 1.f / (1.f + __expf(-v1));
                }
                *reinterpret_cast<float2*>(crow + gn) = make_float2(v0, v1);
                if (split) {
                    __nv_bfloat16 h0 = __float2bfloat16(v0);
                    __nv_bfloat16 h1 = __float2bfloat16(v1);
                    __nv_bfloat16 l0 = __float2bfloat16(v0 - __bfloat162float(h0));
                    __nv_bfloat16 l1 = __float2bfloat16(v1 - __bfloat162float(h1));
                    __nv_bfloat162 hh; hh.x = h0; hh.y = h1;
                    __nv_bfloat162 ll; ll.x = l0; ll.y = l1;
                    __nv_bfloat16* srow = split + (size_t)gm * (3 * (size_t)Nfull) + gn;
                    *reinterpret_cast<__nv_bfloat162*>(srow)             = hh;  // hi
                    *reinterpret_cast<__nv_bfloat162*>(srow + Nfull)     = ll;  // lo
                    *reinterpret_cast<__nv_bfloat162*>(srow + 2 * Nfull) = hh;  // hi
                }
            }
        }
    }
}

// ================= conversion kernels =================
// PAT 0 (A side): (hi, lo, hi)    PAT 1 (B side): (hi, hi, lo)
template<int PAT>
__global__ void split3_kernel(const float* __restrict__ X, __nv_bfloat16* __restrict__ Y,
                              long total, int K)
{
    long i = blockIdx.x * (long)blockDim.x + threadIdx.x;
    if (i >= total) return;
    long m = i / K; int k = (int)(i - m * K);
    float x = X[i];
    __nv_bfloat16 hi = __float2bfloat16(x);
    __nv_bfloat16 lo = __float2bfloat16(x - __bfloat162float(hi));
    __nv_bfloat16* row = Y + m * (3L * K);
    if (PAT == 0) { row[k] = hi; row[K + k] = lo; row[2 * K + k] = hi; }
    else          { row[k] = hi; row[K + k] = hi; row[2 * K + k] = lo; }
}

// X: [K, N] -> Y: [N, 3K] (B side pattern)
__global__ void split3T_kernel(const float* __restrict__ X, __nv_bfloat16* __restrict__ Y,
                               int K, int N)
{
    int i = blockIdx.x * blockDim.x + threadIdx.x;
    if (i >= K * N) return;
    int k = i / N, n = i - k * N;
    float x = X[i];
    __nv_bfloat16 hi = __float2bfloat16(x);
    __nv_bfloat16 lo = __float2bfloat16(x - __bfloat162float(hi));
    __nv_bfloat16* row = Y + (size_t)n * (3 * K);
    row[k] = hi; row[K + k] = hi; row[2 * K + k] = lo;
}

// fused = sig_av*fi + sig_ae*ti, write split (A pattern) directly
__global__ void fuse_split_kernel(const float* __restrict__ av, const float* __restrict__ fi,
                                  const float* __restrict__ ae, const float* __restrict__ ti,
                                  __nv_bfloat16* __restrict__ Y, int n)
{
    int i = blockIdx.x * blockDim.x + threadIdx.x;
    if (i >= n) return;
    float x = av[i] * fi[i] + ae[i] * ti[i];
    int m = i >> 9, k = i & 511;
    __nv_bfloat16 hi = __float2bfloat16(x);
    __nv_bfloat16 lo = __float2bfloat16(x - __bfloat162float(hi));
    __nv_bfloat16* row = Y + (size_t)m * 1536;
    row[k] = hi; row[512 + k] = lo; row[1024 + k] = hi;
}

// h3 = split(elu(hbuf))
__global__ void elu_split_kernel(const float* __restrict__ H, __nv_bfloat16* __restrict__ Y, int n)
{
    int i = blockIdx.x * blockDim.x + threadIdx.x;
    if (i >= n) return;
    float x = H[i];
    x = x > 0.f ? x : expm1f(x);
    int m = i >> 9, k = i & 511;
    __nv_bfloat16 hi = __float2bfloat16(x);
    __nv_bfloat16 lo = __float2bfloat16(x - __bfloat162float(hi));
    __nv_bfloat16* row = Y + (size_t)m * 1536;
    row[k] = hi; row[512 + k] = lo; row[1024 + k] = hi;
}

// ================= misc elementwise =================
__global__ void fill_kernel(float* __restrict__ p, float v, int n) {
    int i = blockIdx.x * blockDim.x + threadIdx.x;
    if (i < n) p[i] = v;
}

// ================= GAT score / softmax / aggregation =================
__global__ void scores_kernel(const float* __restrict__ z, const float* __restrict__ a,
                              float* __restrict__ ssrc, float* __restrict__ sdst,
                              int Nn, int H, int O)
{
    int idx = blockIdx.x * blockDim.x + threadIdx.x;
    if (idx >= Nn * H) return;
    int n = idx / H, h = idx % H;
    const float* zp = z + ((size_t)n * H + h) * O;
    const float* as = a + (size_t)h * 2 * O;
    const float* ad = as + O;
    float s1 = 0.f, s2 = 0.f;
    for (int o = 0; o < O; o += 4) {
        float4 zv = *reinterpret_cast<const float4*>(zp + o);
        s1 = fmaf(zv.x, as[o], fmaf(zv.y, as[o+1], fmaf(zv.z, as[o+2], fmaf(zv.w, as[o+3], s1))));
        s2 = fmaf(zv.x, ad[o], fmaf(zv.y, ad[o+1], fmaf(zv.z, ad[o+2], fmaf(zv.w, ad[o+3], s2))));
    }
    ssrc[idx] = s1;
    sdst[idx] = s2;
}

__device__ __forceinline__ void atomicMaxF(float* addr, float val) {
    if (val >= 0.f) atomicMax((int*)addr, __float_as_int(val));
    else            atomicMin((unsigned int*)addr, __float_as_uint(val));
}

__global__ void edge_logits_kernel(const float* __restrict__ ssrc, const float* __restrict__ sdst,
                                   const int* __restrict__ src, const int* __restrict__ dst,
                                   float* __restrict__ ebuf, float* __restrict__ mbuf,
                                   int E, int H)
{
    int idx = blockIdx.x * blockDim.x + threadIdx.x;
    if (idx >= E * H) return;
    int e = idx / H, h = idx % H;
    int s = src[e], d = dst[e];
    float v = ssrc[(size_t)s * H + h] + sdst[(size_t)d * H + h];
    v = v > 0.f ? v : 0.01f * v;
    ebuf[idx] = v;
    atomicMaxF(&mbuf[(size_t)d * H + h], v);
}

__global__ void edge_exp_kernel(float* __restrict__ ebuf, const int* __restrict__ dst,
                                const float* __restrict__ mbuf, float* __restrict__ den,
                                int E, int H)
{
    int idx = blockIdx.x * blockDim.x + threadIdx.x;
    if (idx >= E * H) return;
    int e = idx / H, h = idx % H;
    int d = dst[e];
    float v = __expf(ebuf[idx] - mbuf[(size_t)d * H + h]);
    ebuf[idx] = v;
    atomicAdd(&den[(size_t)d * H + h], v);
}

__global__ void edge_agg_kernel(const float* __restrict__ ex, const float* __restrict__ den,
                                const int* __restrict__ src, const int* __restrict__ dst,
                                const float* __restrict__ z, float* __restrict__ out,
                                int E, int H, int O)
{
    int idx = blockIdx.x * blockDim.x + threadIdx.x;
    int groups = O / 4;
    int per_edge = H * groups;
    if (idx >= E * per_edge) return;
    int e = idx / per_edge;
    int r = idx % per_edge;
    int h = r / groups;
    int q = r % groups;
    int s = src[e], d = dst[e];
    float coef = ex[(size_t)e * H + h] / den[(size_t)d * H + h];
    const float4 zv = *reinterpret_cast<const float4*>(z + ((size_t)s * H + h) * O + q * 4);
    float* po = out + ((size_t)d * H + h) * O + q * 4;
    asm volatile("red.global.add.v4.f32 [%0], {%1, %2, %3, %4};"
                 :: "l"(po), "f"(coef * zv.x), "f"(coef * zv.y),
                    "f"(coef * zv.z), "f"(coef * zv.w) : "memory");
}

// ================= host orchestration =================
static inline int cdiv(int a, int b) { return (a + b - 1) / b; }

static void launch_gemm(const __nv_bfloat16* A, const __nv_bfloat16* B, float* C,
                        const float* bias, int act, __nv_bfloat16* split,
                        int M, int Nfull, int K3)
{
    static int smem_set = 0;
    const int smem = STAGES * STAGE_BYTES;   // 61440
    if (!smem_set) {
        cudaFuncSetAttribute(gemm_bf16_kernel,
                             cudaFuncAttributeMaxDynamicSharedMemorySize, smem);
        smem_set = 1;
    }
    dim3 grid(Nfull / BNT, cdiv(M, BMT));
    gemm_bf16_kernel<<<grid, 256, smem>>>(A, B, C, bias, act, split, M, Nfull, K3);
}

extern "C" void kernel_launch(void* const* d_in, const int* in_sizes, int n_in,
                              void* d_out, int out_size)
{
    const float* img   = (const float*)d_in[0];
    const float* blk   = (const float*)d_in[1];
    const float* W_img = (const float*)d_in[2];
    const float* W_blk = (const float*)d_in[3];
    const float* Wv    = (const float*)d_in[4];
    const float* bv    = (const float*)d_in[5];
    const float* We    = (const float*)d_in[6];
    const float* be    = (const float*)d_in[7];
    const float* fc1   = (const float*)d_in[8];
    const float* attn1 = (const float*)d_in[9];
    const float* fc2   = (const float*)d_in[10];
    const float* attn2 = (const float*)d_in[11];
    const int* e0s = (const int*)d_in[12];
    const int* e0d = (const int*)d_in[13];
    const int* e1s = (const int*)d_in[14];
    const int* e1d = (const int*)d_in[15];
    float* out = (float*)d_out;

    int E0 = in_sizes[12];
    int E1 = in_sizes[14];

    float *fi, *ti, *av, *ae, *hbuf, *z2;
    float *s1s, *s1d, *e1b, *m1, *d1, *s2s, *s2d, *e2b, *m2, *d2;
    __nv_bfloat16 *img3, *blk3, *fi3, *ti3, *fu3, *h3;
    __nv_bfloat16 *wimg3, *wblk3, *wv3, *we3, *fc13, *fc23;
    cudaGetSymbolAddress((void**)&fi,  g_fi);
    cudaGetSymbolAddress((void**)&ti,  g_ti);
    cudaGetSymbolAddress((void**)&av,  g_av);
    cudaGetSymbolAddress((void**)&ae,  g_ae);
    cudaGetSymbolAddress((void**)&hbuf,g_h);
    cudaGetSymbolAddress((void**)&z2,  g_z2);
    cudaGetSymbolAddress((void**)&s1s, g_s1s);
    cudaGetSymbolAddress((void**)&s1d, g_s1d);
    cudaGetSymbolAddress((void**)&e1b, g_e1);
    cudaGetSymbolAddress((void**)&m1,  g_m1);
    cudaGetSymbolAddress((void**)&d1,  g_d1);
    cudaGetSymbolAddress((void**)&s2s, g_s2s);
    cudaGetSymbolAddress((void**)&s2d, g_s2d);
    cudaGetSymbolAddress((void**)&e2b, g_e2);
    cudaGetSymbolAddress((void**)&m2,  g_m2);
    cudaGetSymbolAddress((void**)&d2,  g_d2);
    cudaGetSymbolAddress((void**)&img3, g_img3);
    cudaGetSymbolAddress((void**)&blk3, g_blk3);
    cudaGetSymbolAddress((void**)&fi3,  g_fi3);
    cudaGetSymbolAddress((void**)&ti3,  g_ti3);
    cudaGetSymbolAddress((void**)&fu3,  g_fu3);
    cudaGetSymbolAddress((void**)&h3,   g_h3);
    cudaGetSymbolAddress((void**)&wimg3, g_wimg3);
    cudaGetSymbolAddress((void**)&wblk3, g_wblk3);
    cudaGetSymbolAddress((void**)&wv3,   g_wv3);
    cudaGetSymbolAddress((void**)&we3,   g_we3);
    cudaGetSymbolAddress((void**)&fc13,  g_fc13);
    cudaGetSymbolAddress((void**)&fc23,  g_fc23);

    const float NEG_INF = -INFINITY;

    // --- init accumulators / outputs ---
    {
        int n;
        n = NDST0 * FUSED_D; fill_kernel<<<cdiv(n,256),256>>>(hbuf, 0.f, n);
        n = NDST1 * O2;      fill_kernel<<<cdiv(n,256),256>>>(out,  0.f, n);
        n = NDST0 * H1;      fill_kernel<<<cdiv(n,256),256>>>(m1, NEG_INF, n);
        n = NDST0 * H1;      fill_kernel<<<cdiv(n,256),256>>>(d1, 0.f, n);
        n = NDST1;           fill_kernel<<<cdiv(n,256),256>>>(m2, NEG_INF, n);
        n = NDST1;           fill_kernel<<<cdiv(n,256),256>>>(d2, 0.f, n);
    }

    // --- weight conversions (small) ---
    split3_kernel<1><<<cdiv(512*IMG_D,256),256>>>(W_img, wimg3, (long)512*IMG_D, IMG_D);
    split3_kernel<1><<<cdiv(512*BLK_D,256),256>>>(W_blk, wblk3, (long)512*BLK_D, BLK_D);
    split3T_kernel<<<cdiv(512*512,256),256>>>(Wv, wv3, 512, 512);
    split3T_kernel<<<cdiv(512*512,256),256>>>(We, we3, 512, 512);
    split3_kernel<1><<<cdiv(512*512,256),256>>>(fc1, fc13, (long)512*512, 512);
    split3_kernel<1><<<cdiv(128*512,256),256>>>(fc2, fc23, (long)128*512, 512);

    // --- input conversions ---
    {
        long n = (long)NSRC0 * IMG_D;
        split3_kernel<0><<<(int)((n + 255) / 256), 256>>>(img, img3, n, IMG_D);
    }
    {
        long n = (long)NSRC0 * BLK_D;
        split3_kernel<0><<<(int)((n + 255) / 256), 256>>>(blk, blk3, n, BLK_D);
    }

    // --- CrossAttentionLayer ---
    // fi = img @ W_img^T   (+ split write of fi3 for the gating GEMM)
    launch_gemm(img3, wimg3, fi, nullptr, 0, fi3, NSRC0, FUSED_D, 3*IMG_D);
    // ti = blk @ W_blk^T
    launch_gemm(blk3, wblk3, ti, nullptr, 0, ti3, NSRC0, FUSED_D, 3*BLK_D);
    // av = sigmoid(fi @ Wv + bv)
    launch_gemm(fi3, wv3, av, bv, 1, nullptr, NSRC0, FUSED_D, 3*FUSED_D);
    // ae = sigmoid(ti @ We + be)
    launch_gemm(ti3, we3, ae, be, 1, nullptr, NSRC0, FUSED_D, 3*FUSED_D);
    // fused (split form only)
    {
        int n = NSRC0 * FUSED_D;
        fuse_split_kernel<<<cdiv(n,256),256>>>(av, fi, ae, ti, fu3, n);
    }

    // --- Layer 1: 8-head GAT ---
    // z1 = fused @ fc1^T  -> into g_fi (fp32)
    launch_gemm(fu3, fc13, fi, nullptr, 0, nullptr, NSRC0, FUSED_D, 3*FUSED_D);
    {
        int n = NSRC0 * H1;
        scores_kernel<<<cdiv(n,256),256>>>(fi, attn1, s1s, s1d, NSRC0, H1, O1);
    }
    {
        int n = E0 * H1;
        edge_logits_kernel<<<cdiv(n,256),256>>>(s1s, s1d, e0s, e0d, e1b, m1, E0, H1);
        edge_exp_kernel<<<cdiv(n,256),256>>>(e1b, e0d, m1, d1, E0, H1);
        int na = E0 * H1 * (O1/4);
        edge_agg_kernel<<<cdiv(na,256),256>>>(e1b, d1, e0s, e0d, fi, hbuf, E0, H1, O1);
    }
    // h3 = split(elu(hbuf))
    {
        int n = NDST0 * FUSED_D;
        elu_split_kernel<<<cdiv(n,256),256>>>(hbuf, h3, n);
    }

    // --- Layer 2: 1-head GAT ---
    // z2 = h @ fc2^T  [30000,128]
    launch_gemm(h3, fc23, z2, nullptr, 0, nullptr, NDST0, O2, 3*FUSED_D);
    {
        int n = NDST0;
        scores_kernel<<<cdiv(n,256),256>>>(z2, attn2, s2s, s2d, NDST0, 1, O2);
    }
    {
        int n = E1;
        edge_logits_kernel<<<cdiv(n,256),256>>>(s2s, s2d, e1s, e1d, e2b, m2, E1, 1);
        edge_exp_kernel<<<cdiv(n,256),256>>>(e2b, e1d, m2, d2, E1, 1);
        int na = E1 * (O2/4);
        edge_agg_kernel<<<cdiv(na,256),256>>>(e2b, d2, e1s, e1d, z2, out, E1, 1, O2);
    }

    (void)n_in; (void)out_size; (void)in_sizes;
}

// round 11
// speedup vs baseline: 2.3100x; 1.0140x over previous
#include <cuda_runtime.h>
#include <cuda_bf16.h>
#include <math.h>
#include <stdint.h>

// ---------------- Problem constants ----------------
#define NSRC0   60000
#define NDST0   30000
#define NE0     480000
#define NDST1   8000
#define NE1     128000
#define IMG_D   1024
#define BLK_D   768
#define FUSED_D 512
#define H1      8
#define O1      64
#define O2      128

// ---------------- fp32 scratch ----------------
__device__ float g_fi[(size_t)NSRC0 * FUSED_D];   // fi, later z1
__device__ float g_ti[(size_t)NSRC0 * FUSED_D];
__device__ float g_av[(size_t)NSRC0 * FUSED_D];
__device__ float g_ae[(size_t)NSRC0 * FUSED_D];
__device__ float g_h [(size_t)NDST0 * FUSED_D];
__device__ float g_z2[(size_t)NDST0 * O2];
__device__ float g_s1s[(size_t)NSRC0 * H1];
__device__ float g_s1d[(size_t)NSRC0 * H1];
__device__ float g_e1 [(size_t)NE0   * H1];
__device__ float g_d1 [(size_t)NDST0 * H1];
__device__ float g_s2s[(size_t)NDST0];
__device__ float g_s2d[(size_t)NDST0];
__device__ float g_e2 [(size_t)NE1];
__device__ float g_d2 [(size_t)NDST1];

// ---------------- bf16 split-triplet scratch ----------------
__device__ __nv_bfloat16 g_img3[(size_t)NSRC0 * 3 * IMG_D];
__device__ __nv_bfloat16 g_blk3[(size_t)NSRC0 * 3 * BLK_D];
__device__ __nv_bfloat16 g_fi3 [(size_t)NSRC0 * 3 * FUSED_D];
__device__ __nv_bfloat16 g_ti3 [(size_t)NSRC0 * 3 * FUSED_D];
__device__ __nv_bfloat16 g_fu3 [(size_t)NSRC0 * 3 * FUSED_D];
__device__ __nv_bfloat16 g_h3  [(size_t)NDST0 * 3 * FUSED_D];
__device__ __nv_bfloat16 g_wimg3[512 * 3 * IMG_D];
__device__ __nv_bfloat16 g_wblk3[512 * 3 * BLK_D];
__device__ __nv_bfloat16 g_wv3  [512 * 3 * FUSED_D];
__device__ __nv_bfloat16 g_we3  [512 * 3 * FUSED_D];
__device__ __nv_bfloat16 g_fc13 [512 * 3 * FUSED_D];
__device__ __nv_bfloat16 g_fc23 [128 * 3 * FUSED_D];

// ================= PTX helpers (family-profile-safe only) =================
__device__ __forceinline__ uint32_t smem_u32(const void* p) {
    return (uint32_t)__cvta_generic_to_shared(p);
}

__device__ __forceinline__ void cp_async16(uint32_t dst, const void* src, int sz) {
    asm volatile("cp.async.cg.shared.global [%0], [%1], 16, %2;"
                 :: "r"(dst), "l"(src), "r"(sz));
}
#define CP_COMMIT() asm volatile("cp.async.commit_group;" ::: "memory")

__device__ __forceinline__ void ldsm4(uint32_t* r, uint32_t addr) {
    asm volatile("ldmatrix.sync.aligned.m8n8.x4.shared.b16 {%0,%1,%2,%3}, [%4];"
                 : "=r"(r[0]), "=r"(r[1]), "=r"(r[2]), "=r"(r[3]) : "r"(addr));
}

__device__ __forceinline__ void mma_bf16(float* c, const uint32_t* a, const uint32_t* b) {
    asm volatile(
        "mma.sync.aligned.m16n8k16.row.col.f32.bf16.bf16.f32 "
        "{%0,%1,%2,%3}, {%4,%5,%6,%7}, {%8,%9}, {%0,%1,%2,%3};"
        : "+f"(c[0]), "+f"(c[1]), "+f"(c[2]), "+f"(c[3])
        : "r"(a[0]), "r"(a[1]), "r"(a[2]), "r"(a[3]), "r"(b[0]), "r"(b[1]));
}

// ================= bf16 HMMA GEMM =================
// C[M,Nfull] = A[M,K] * B[Nfull,K]^T  (bf16 K-major rows), fp32 accumulate.
// Tile 128x128xBK32, 3-stage cp.async pipeline, 8 warps @ 64x32, 2 CTAs/SM.
#define BMT 128
#define BNT 128
#define BKT 32
#define STAGES 3
#define ROWB 80                 // 32 halves + 8 pad halves = 80 bytes/row
#define STAGE_BYTES ((BMT + BNT) * ROWB)   // 20480

__global__ void __launch_bounds__(256, 2)
gemm_bf16_kernel(const __nv_bfloat16* __restrict__ A,
                 const __nv_bfloat16* __restrict__ B,
                 float* __restrict__ C,
                 const float* __restrict__ bias, int act,
                 __nv_bfloat16* __restrict__ split,
                 int M, int Nfull, int K)
{
    extern __shared__ char smem[];
    const int tid = threadIdx.x;
    const int lane = tid & 31, wid = tid >> 5;
    const int bm = blockIdx.y * BMT;
    const int bn = blockIdx.x * BNT;
    const int wm = (wid >> 2) * 64;      // 2 warp-rows
    const int wn = (wid & 3) * 32;       // 4 warp-cols
    const int T = K / BKT;
    const uint32_t sb = smem_u32(smem);

    float acc[4][4][4];
    #pragma unroll
    for (int i = 0; i < 4; i++)
        #pragma unroll
        for (int j = 0; j < 4; j++)
            #pragma unroll
            for (int k = 0; k < 4; k++) acc[i][j][k] = 0.f;

    // ---- stage loader: A rows then B rows, 16B chunks ----
    auto load_stage = [&](int t, int s) {
        uint32_t base = sb + (uint32_t)s * STAGE_BYTES;
        const __nv_bfloat16* Ab = A + (size_t)bm * K + (size_t)t * BKT;
        const __nv_bfloat16* Bb = B + (size_t)bn * K + (size_t)t * BKT;
        #pragma unroll
        for (int i = tid; i < 1024; i += 256) {
            int row = (i >> 2) & 127;
            int ch  = i & 3;
            if (i < 512) {
                int ok = (bm + row < M);
                const __nv_bfloat16* src = Ab + (size_t)(ok ? row : 0) * K + ch * 8;
                cp_async16(base + row * ROWB + ch * 16, src, ok ? 16 : 0);
            } else {
                cp_async16(base + (BMT + row) * ROWB + ch * 16,
                           Bb + (size_t)row * K + ch * 8, 16);
            }
        }
        CP_COMMIT();
    };

    // prologue
    #pragma unroll
    for (int s = 0; s < STAGES; s++) load_stage(s, s);

    for (int t = 0; t < T; t++) {
        asm volatile("cp.async.wait_group %0;" :: "n"(STAGES - 1));
        __syncthreads();
        uint32_t Abase = sb + (uint32_t)(t % STAGES) * STAGE_BYTES;
        uint32_t Bbase = Abase + BMT * ROWB;
        const int rsel = lane & 15;

        #pragma unroll
        for (int ks = 0; ks < 2; ks++) {
            uint32_t koff = (uint32_t)(ks * 32 + (lane >> 4) * 16);
            uint32_t a[4][4], b[4][2];
            #pragma unroll
            for (int mi = 0; mi < 4; mi++)
                ldsm4(a[mi], Abase + (uint32_t)(wm + 16 * mi + rsel) * ROWB + koff);
            #pragma unroll
            for (int bj = 0; bj < 2; bj++) {
                uint32_t r[4];
                ldsm4(r, Bbase + (uint32_t)(wn + 16 * bj + rsel) * ROWB + koff);
                b[2*bj][0] = r[0]; b[2*bj][1] = r[2];
                b[2*bj+1][0] = r[1]; b[2*bj+1][1] = r[3];
            }
            #pragma unroll
            for (int mi = 0; mi < 4; mi++)
                #pragma unroll
                for (int nj = 0; nj < 4; nj++)
                    mma_bf16(acc[mi][nj], a[mi], b[nj]);
        }
        __syncthreads();
        if (t + STAGES < T) load_stage(t + STAGES, t % STAGES);
        else CP_COMMIT();   // empty group keeps wait_group counting uniform
    }

    // ---- epilogue: bias / sigmoid / fp32 store / optional bf16 split store ----
    #pragma unroll
    for (int mi = 0; mi < 4; mi++) {
        #pragma unroll
        for (int half = 0; half < 2; half++) {
            int gm = bm + wm + 16 * mi + (lane >> 2) + 8 * half;
            if (gm >= M) continue;
            float* crow = C + (size_t)gm * Nfull;
            #pragma unroll
            for (int nj = 0; nj < 4; nj++) {
                int gn = bn + wn + 8 * nj + 2 * (lane & 3);
                float v0 = acc[mi][nj][2 * half + 0];
                float v1 = acc[mi][nj][2 * half + 1];
                if (bias) { v0 += bias[gn]; v1 += bias[gn + 1]; }
                if (act) {
                    v0 = 1.f / (1.f + __expf(-v0));
                    v1 = 1.f / (1.f + __expf(-v1));
                }
                *reinterpret_cast<float2*>(crow + gn) = make_float2(v0, v1);
                if (split) {
                    __nv_bfloat16 h0 = __float2bfloat16(v0);
                    __nv_bfloat16 h1 = __float2bfloat16(v1);
                    __nv_bfloat16 l0 = __float2bfloat16(v0 - __bfloat162float(h0));
                    __nv_bfloat16 l1 = __float2bfloat16(v1 - __bfloat162float(h1));
                    __nv_bfloat162 hh; hh.x = h0; hh.y = h1;
                    __nv_bfloat162 ll; ll.x = l0; ll.y = l1;
                    __nv_bfloat16* srow = split + (size_t)gm * (3 * (size_t)Nfull) + gn;
                    *reinterpret_cast<__nv_bfloat162*>(srow)             = hh;  // hi
                    *reinterpret_cast<__nv_bfloat162*>(srow + Nfull)     = ll;  // lo
                    *reinterpret_cast<__nv_bfloat162*>(srow + 2 * Nfull) = hh;  // hi
                }
            }
        }
    }
}

// ================= conversion kernels =================
// PAT 0 (A side): (hi, lo, hi)    PAT 1 (B side): (hi, hi, lo)
template<int PAT>
__global__ void split3_kernel(const float* __restrict__ X, __nv_bfloat16* __restrict__ Y,
                              long total, int K)
{
    long i = blockIdx.x * (long)blockDim.x + threadIdx.x;
    if (i >= total) return;
    long m = i / K; int k = (int)(i - m * K);
    float x = X[i];
    __nv_bfloat16 hi = __float2bfloat16(x);
    __nv_bfloat16 lo = __float2bfloat16(x - __bfloat162float(hi));
    __nv_bfloat16* row = Y + m * (3L * K);
    if (PAT == 0) { row[k] = hi; row[K + k] = lo; row[2 * K + k] = hi; }
    else          { row[k] = hi; row[K + k] = hi; row[2 * K + k] = lo; }
}

// X: [K, N] -> Y: [N, 3K] (B side pattern)
__global__ void split3T_kernel(const float* __restrict__ X, __nv_bfloat16* __restrict__ Y,
                               int K, int N)
{
    int i = blockIdx.x * blockDim.x + threadIdx.x;
    if (i >= K * N) return;
    int k = i / N, n = i - k * N;
    float x = X[i];
    __nv_bfloat16 hi = __float2bfloat16(x);
    __nv_bfloat16 lo = __float2bfloat16(x - __bfloat162float(hi));
    __nv_bfloat16* row = Y + (size_t)n * (3 * K);
    row[k] = hi; row[K + k] = hi; row[2 * K + k] = lo;
}

// fused = sig_av*fi + sig_ae*ti, write split (A pattern) directly
__global__ void fuse_split_kernel(const float* __restrict__ av, const float* __restrict__ fi,
                                  const float* __restrict__ ae, const float* __restrict__ ti,
                                  __nv_bfloat16* __restrict__ Y, int n)
{
    int i = blockIdx.x * blockDim.x + threadIdx.x;
    if (i >= n) return;
    float x = av[i] * fi[i] + ae[i] * ti[i];
    int m = i >> 9, k = i & 511;
    __nv_bfloat16 hi = __float2bfloat16(x);
    __nv_bfloat16 lo = __float2bfloat16(x - __bfloat162float(hi));
    __nv_bfloat16* row = Y + (size_t)m * 1536;
    row[k] = hi; row[512 + k] = lo; row[1024 + k] = hi;
}

// h3 = split(elu(hbuf))
__global__ void elu_split_kernel(const float* __restrict__ H, __nv_bfloat16* __restrict__ Y, int n)
{
    int i = blockIdx.x * blockDim.x + threadIdx.x;
    if (i >= n) return;
    float x = H[i];
    x = x > 0.f ? x : expm1f(x);
    int m = i >> 9, k = i & 511;
    __nv_bfloat16 hi = __float2bfloat16(x);
    __nv_bfloat16 lo = __float2bfloat16(x - __bfloat162float(hi));
    __nv_bfloat16* row = Y + (size_t)m * 1536;
    row[k] = hi; row[512 + k] = lo; row[1024 + k] = hi;
}

// ================= misc elementwise =================
__global__ void fill_kernel(float* __restrict__ p, float v, int n) {
    int i = blockIdx.x * blockDim.x + threadIdx.x;
    if (i < n) p[i] = v;
}

// ================= GAT score / softmax / aggregation =================
// Warp-collective: one warp per (node, head). Coalesced float2 loads + shfl reduce.
__global__ void scores_warp_kernel(const float* __restrict__ z, const float* __restrict__ a,
                                   float* __restrict__ ssrc, float* __restrict__ sdst,
                                   int Nn, int H, int O)
{
    int gw = (blockIdx.x * blockDim.x + threadIdx.x) >> 5;
    int lane = threadIdx.x & 31;
    if (gw >= Nn * H) return;
    int n = gw / H, h = gw - n * H;
    const float2* zp = reinterpret_cast<const float2*>(z + ((size_t)n * H + h) * O);
    const float2* as = reinterpret_cast<const float2*>(a + (size_t)h * 2 * O);
    const float2* ad = reinterpret_cast<const float2*>(a + (size_t)h * 2 * O + O);
    float s1 = 0.f, s2 = 0.f;
    for (int o = lane; o < (O >> 1); o += 32) {
        float2 zv = zp[o];
        float2 a1 = as[o], a2 = ad[o];
        s1 = fmaf(zv.x, a1.x, fmaf(zv.y, a1.y, s1));
        s2 = fmaf(zv.x, a2.x, fmaf(zv.y, a2.y, s2));
    }
    #pragma unroll
    for (int off = 16; off > 0; off >>= 1) {
        s1 += __shfl_xor_sync(0xFFFFFFFF, s1, off);
        s2 += __shfl_xor_sync(0xFFFFFFFF, s2, off);
    }
    if (lane == 0) { ssrc[gw] = s1; sdst[gw] = s2; }
}

// Single-pass softmax numerator + denominator (no max shift: logits are O(10),
// exp is safely finite in fp32; identical math to the shifted reference).
__global__ void edge_soft_kernel(const float* __restrict__ ssrc, const float* __restrict__ sdst,
                                 const int* __restrict__ src, const int* __restrict__ dst,
                                 float* __restrict__ ebuf, float* __restrict__ den,
                                 int E, int H)
{
    int idx = blockIdx.x * blockDim.x + threadIdx.x;
    if (idx >= E * H) return;
    int e = idx / H, h = idx - e * H;
    int s = src[e], d = dst[e];
    float v = ssrc[(size_t)s * H + h] + sdst[(size_t)d * H + h];
    v = v > 0.f ? v : 0.01f * v;           // leaky_relu(0.01)
    float ex = __expf(v);
    ebuf[idx] = ex;
    asm volatile("red.global.add.f32 [%0], %1;"
                 :: "l"(den + (size_t)d * H + h), "f"(ex) : "memory");
}

__global__ void edge_agg_kernel(const float* __restrict__ ex, const float* __restrict__ den,
                                const int* __restrict__ src, const int* __restrict__ dst,
                                const float* __restrict__ z, float* __restrict__ out,
                                int E, int H, int O)
{
    int idx = blockIdx.x * blockDim.x + threadIdx.x;
    int groups = O / 4;
    int per_edge = H * groups;
    if (idx >= E * per_edge) return;
    int e = idx / per_edge;
    int r = idx % per_edge;
    int h = r / groups;
    int q = r % groups;
    int s = src[e], d = dst[e];
    float coef = ex[(size_t)e * H + h] / den[(size_t)d * H + h];
    const float4 zv = *reinterpret_cast<const float4*>(z + ((size_t)s * H + h) * O + q * 4);
    float* po = out + ((size_t)d * H + h) * O + q * 4;
    asm volatile("red.global.add.v4.f32 [%0], {%1, %2, %3, %4};"
                 :: "l"(po), "f"(coef * zv.x), "f"(coef * zv.y),
                    "f"(coef * zv.z), "f"(coef * zv.w) : "memory");
}

// ================= host orchestration =================
static inline int cdiv(int a, int b) { return (a + b - 1) / b; }

static void launch_gemm(const __nv_bfloat16* A, const __nv_bfloat16* B, float* C,
                        const float* bias, int act, __nv_bfloat16* split,
                        int M, int Nfull, int K3)
{
    static int smem_set = 0;
    const int smem = STAGES * STAGE_BYTES;   // 61440
    if (!smem_set) {
        cudaFuncSetAttribute(gemm_bf16_kernel,
                             cudaFuncAttributeMaxDynamicSharedMemorySize, smem);
        smem_set = 1;
    }
    dim3 grid(Nfull / BNT, cdiv(M, BMT));
    gemm_bf16_kernel<<<grid, 256, smem>>>(A, B, C, bias, act, split, M, Nfull, K3);
}

extern "C" void kernel_launch(void* const* d_in, const int* in_sizes, int n_in,
                              void* d_out, int out_size)
{
    const float* img   = (const float*)d_in[0];
    const float* blk   = (const float*)d_in[1];
    const float* W_img = (const float*)d_in[2];
    const float* W_blk = (const float*)d_in[3];
    const float* Wv    = (const float*)d_in[4];
    const float* bv    = (const float*)d_in[5];
    const float* We    = (const float*)d_in[6];
    const float* be    = (const float*)d_in[7];
    const float* fc1   = (const float*)d_in[8];
    const float* attn1 = (const float*)d_in[9];
    const float* fc2   = (const float*)d_in[10];
    const float* attn2 = (const float*)d_in[11];
    const int* e0s = (const int*)d_in[12];
    const int* e0d = (const int*)d_in[13];
    const int* e1s = (const int*)d_in[14];
    const int* e1d = (const int*)d_in[15];
    float* out = (float*)d_out;

    int E0 = in_sizes[12];
    int E1 = in_sizes[14];

    float *fi, *ti, *av, *ae, *hbuf, *z2;
    float *s1s, *s1d, *e1b, *d1, *s2s, *s2d, *e2b, *d2;
    __nv_bfloat16 *img3, *blk3, *fi3, *ti3, *fu3, *h3;
    __nv_bfloat16 *wimg3, *wblk3, *wv3, *we3, *fc13, *fc23;
    cudaGetSymbolAddress((void**)&fi,  g_fi);
    cudaGetSymbolAddress((void**)&ti,  g_ti);
    cudaGetSymbolAddress((void**)&av,  g_av);
    cudaGetSymbolAddress((void**)&ae,  g_ae);
    cudaGetSymbolAddress((void**)&hbuf,g_h);
    cudaGetSymbolAddress((void**)&z2,  g_z2);
    cudaGetSymbolAddress((void**)&s1s, g_s1s);
    cudaGetSymbolAddress((void**)&s1d, g_s1d);
    cudaGetSymbolAddress((void**)&e1b, g_e1);
    cudaGetSymbolAddress((void**)&d1,  g_d1);
    cudaGetSymbolAddress((void**)&s2s, g_s2s);
    cudaGetSymbolAddress((void**)&s2d, g_s2d);
    cudaGetSymbolAddress((void**)&e2b, g_e2);
    cudaGetSymbolAddress((void**)&d2,  g_d2);
    cudaGetSymbolAddress((void**)&img3, g_img3);
    cudaGetSymbolAddress((void**)&blk3, g_blk3);
    cudaGetSymbolAddress((void**)&fi3,  g_fi3);
    cudaGetSymbolAddress((void**)&ti3,  g_ti3);
    cudaGetSymbolAddress((void**)&fu3,  g_fu3);
    cudaGetSymbolAddress((void**)&h3,   g_h3);
    cudaGetSymbolAddress((void**)&wimg3, g_wimg3);
    cudaGetSymbolAddress((void**)&wblk3, g_wblk3);
    cudaGetSymbolAddress((void**)&wv3,   g_wv3);
    cudaGetSymbolAddress((void**)&we3,   g_we3);
    cudaGetSymbolAddress((void**)&fc13,  g_fc13);
    cudaGetSymbolAddress((void**)&fc23,  g_fc23);

    // --- init accumulators / outputs (no more -inf max buffers) ---
    {
        int n;
        n = NDST0 * FUSED_D; fill_kernel<<<cdiv(n,256),256>>>(hbuf, 0.f, n);
        n = NDST1 * O2;      fill_kernel<<<cdiv(n,256),256>>>(out,  0.f, n);
        n = NDST0 * H1;      fill_kernel<<<cdiv(n,256),256>>>(d1, 0.f, n);
        n = NDST1;           fill_kernel<<<cdiv(n,256),256>>>(d2, 0.f, n);
    }

    // --- weight conversions (small) ---
    split3_kernel<1><<<cdiv(512*IMG_D,256),256>>>(W_img, wimg3, (long)512*IMG_D, IMG_D);
    split3_kernel<1><<<cdiv(512*BLK_D,256),256>>>(W_blk, wblk3, (long)512*BLK_D, BLK_D);
    split3T_kernel<<<cdiv(512*512,256),256>>>(Wv, wv3, 512, 512);
    split3T_kernel<<<cdiv(512*512,256),256>>>(We, we3, 512, 512);
    split3_kernel<1><<<cdiv(512*512,256),256>>>(fc1, fc13, (long)512*512, 512);
    split3_kernel<1><<<cdiv(128*512,256),256>>>(fc2, fc23, (long)128*512, 512);

    // --- input conversions ---
    {
        long n = (long)NSRC0 * IMG_D;
        split3_kernel<0><<<(int)((n + 255) / 256), 256>>>(img, img3, n, IMG_D);
    }
    {
        long n = (long)NSRC0 * BLK_D;
        split3_kernel<0><<<(int)((n + 255) / 256), 256>>>(blk, blk3, n, BLK_D);
    }

    // --- CrossAttentionLayer ---
    launch_gemm(img3, wimg3, fi, nullptr, 0, fi3, NSRC0, FUSED_D, 3*IMG_D);
    launch_gemm(blk3, wblk3, ti, nullptr, 0, ti3, NSRC0, FUSED_D, 3*BLK_D);
    launch_gemm(fi3, wv3, av, bv, 1, nullptr, NSRC0, FUSED_D, 3*FUSED_D);
    launch_gemm(ti3, we3, ae, be, 1, nullptr, NSRC0, FUSED_D, 3*FUSED_D);
    {
        int n = NSRC0 * FUSED_D;
        fuse_split_kernel<<<cdiv(n,256),256>>>(av, fi, ae, ti, fu3, n);
    }

    // --- Layer 1: 8-head GAT ---
    launch_gemm(fu3, fc13, fi, nullptr, 0, nullptr, NSRC0, FUSED_D, 3*FUSED_D);
    {
        int nw = NSRC0 * H1;                       // one warp per (node, head)
        scores_warp_kernel<<<cdiv(nw * 32, 256), 256>>>(fi, attn1, s1s, s1d, NSRC0, H1, O1);
    }
    {
        int n = E0 * H1;
        edge_soft_kernel<<<cdiv(n,256),256>>>(s1s, s1d, e0s, e0d, e1b, d1, E0, H1);
        int na = E0 * H1 * (O1/4);
        edge_agg_kernel<<<cdiv(na,256),256>>>(e1b, d1, e0s, e0d, fi, hbuf, E0, H1, O1);
    }
    {
        int n = NDST0 * FUSED_D;
        elu_split_kernel<<<cdiv(n,256),256>>>(hbuf, h3, n);
    }

    // --- Layer 2: 1-head GAT ---
    launch_gemm(h3, fc23, z2, nullptr, 0, nullptr, NDST0, O2, 3*FUSED_D);
    {
        int nw = NDST0;
        scores_warp_kernel<<<cdiv(nw * 32, 256), 256>>>(z2, attn2, s2s, s2d, NDST0, 1, O2);
    }
    {
        int n = E1;
        edge_soft_kernel<<<cdiv(n,256),256>>>(s2s, s2d, e1s, e1d, e2b, d2, E1, 1);
        int na = E1 * (O2/4);
        edge_agg_kernel<<<cdiv(na,256),256>>>(e2b, d2, e1s, e1d, z2, out, E1, 1, O2);
    }

    (void)n_in; (void)out_size; (void)in_sizes;
}

// round 16
// speedup vs baseline: 2.7219x; 1.1783x over previous
#include <cuda_runtime.h>
#include <cuda_fp16.h>
#include <math.h>
#include <stdint.h>

// ---------------- Problem constants ----------------
#define NSRC0   60000
#define NDST0   30000
#define NE0     480000
#define NDST1   8000
#define NE1     128000
#define IMG_D   1024
#define BLK_D   768
#define FUSED_D 512
#define H1      8
#define O1      64
#define O2      128

// ---------------- fp32 scratch ----------------
__device__ float g_fi[(size_t)NSRC0 * FUSED_D];   // fi, later z1
__device__ float g_ti[(size_t)NSRC0 * FUSED_D];
__device__ float g_av[(size_t)NSRC0 * FUSED_D];
__device__ float g_ae[(size_t)NSRC0 * FUSED_D];
__device__ float g_h [(size_t)NDST0 * FUSED_D];
__device__ float g_z2[(size_t)NDST0 * O2];
__device__ float g_s1s[(size_t)NSRC0 * H1];
__device__ float g_s1d[(size_t)NSRC0 * H1];
__device__ float g_e1 [(size_t)NE0   * H1];
__device__ float g_d1 [(size_t)NDST0 * H1];
__device__ float g_s2s[(size_t)NDST0];
__device__ float g_s2d[(size_t)NDST0];
__device__ float g_e2 [(size_t)NE1];
__device__ float g_d2 [(size_t)NDST1];

// ---------------- fp16 split scratch ----------------
__device__ __half g_img3[(size_t)NSRC0 * 3 * IMG_D];   // A 3-term (hi,lo,hi)
__device__ __half g_blk3[(size_t)NSRC0 * 3 * BLK_D];
__device__ __half g_fi1 [(size_t)NSRC0 * FUSED_D];     // 1-term fp16 fi (gate input)
__device__ __half g_ti1 [(size_t)NSRC0 * FUSED_D];
__device__ __half g_fu3 [(size_t)NSRC0 * 3 * FUSED_D];
__device__ __half g_h3  [(size_t)NDST0 * 3 * FUSED_D];
__device__ __half g_wimg3[512 * 3 * IMG_D];            // B 3-term (hi,hi,lo)
__device__ __half g_wblk3[512 * 3 * BLK_D];
__device__ __half g_wv1  [512 * FUSED_D];              // 1-term fp16 Wv^T
__device__ __half g_we1  [512 * FUSED_D];
__device__ __half g_fc13 [512 * 3 * FUSED_D];
__device__ __half g_fc23 [128 * 3 * FUSED_D];

// ================= PTX helpers (family-profile-safe only) =================
__device__ __forceinline__ uint32_t smem_u32(const void* p) {
    return (uint32_t)__cvta_generic_to_shared(p);
}

__device__ __forceinline__ void cp_async16(uint32_t dst, const void* src, int sz) {
    asm volatile("cp.async.cg.shared.global [%0], [%1], 16, %2;"
                 :: "r"(dst), "l"(src), "r"(sz));
}
#define CP_COMMIT() asm volatile("cp.async.commit_group;" ::: "memory")

__device__ __forceinline__ void ldsm4(uint32_t* r, uint32_t addr) {
    asm volatile("ldmatrix.sync.aligned.m8n8.x4.shared.b16 {%0,%1,%2,%3}, [%4];"
                 : "=r"(r[0]), "=r"(r[1]), "=r"(r[2]), "=r"(r[3]) : "r"(addr));
}

__device__ __forceinline__ void mma_f16(float* c, const uint32_t* a, const uint32_t* b) {
    asm volatile(
        "mma.sync.aligned.m16n8k16.row.col.f32.f16.f16.f32 "
        "{%0,%1,%2,%3}, {%4,%5,%6,%7}, {%8,%9}, {%0,%1,%2,%3};"
        : "+f"(c[0]), "+f"(c[1]), "+f"(c[2]), "+f"(c[3])
        : "r"(a[0]), "r"(a[1]), "r"(a[2]), "r"(a[3]), "r"(b[0]), "r"(b[1]));
}

// ================= fp16 HMMA GEMM =================
// C[M,Nfull] = A[M,K] * B[Nfull,K]^T  (fp16 K-major rows), fp32 accumulate.
// Tile 128x128xBK32, 3-stage cp.async pipeline, 8 warps @ 64x32, 2 CTAs/SM.
#define BMT 128
#define BNT 128
#define BKT 32
#define STAGES 3
#define ROWB 80                 // 32 halves + 8 pad halves = 80 bytes/row
#define STAGE_BYTES ((BMT + BNT) * ROWB)   // 20480

__global__ void __launch_bounds__(256, 2)
gemm_f16_kernel(const __half* __restrict__ A,
                const __half* __restrict__ B,
                float* __restrict__ C,
                const float* __restrict__ bias, int act,
                __half* __restrict__ out16,
                int M, int Nfull, int K)
{
    extern __shared__ char smem[];
    const int tid = threadIdx.x;
    const int lane = tid & 31, wid = tid >> 5;
    const int bm = blockIdx.y * BMT;
    const int bn = blockIdx.x * BNT;
    const int wm = (wid >> 2) * 64;      // 2 warp-rows
    const int wn = (wid & 3) * 32;       // 4 warp-cols
    const int T = K / BKT;
    const uint32_t sb = smem_u32(smem);

    float acc[4][4][4];
    #pragma unroll
    for (int i = 0; i < 4; i++)
        #pragma unroll
        for (int j = 0; j < 4; j++)
            #pragma unroll
            for (int k = 0; k < 4; k++) acc[i][j][k] = 0.f;

    // ---- stage loader: A rows then B rows, 16B chunks ----
    auto load_stage = [&](int t, int s) {
        uint32_t base = sb + (uint32_t)s * STAGE_BYTES;
        const __half* Ab = A + (size_t)bm * K + (size_t)t * BKT;
        const __half* Bb = B + (size_t)bn * K + (size_t)t * BKT;
        #pragma unroll
        for (int i = tid; i < 1024; i += 256) {
            int row = (i >> 2) & 127;
            int ch  = i & 3;
            if (i < 512) {
                int ok = (bm + row < M);
                const __half* src = Ab + (size_t)(ok ? row : 0) * K + ch * 8;
                cp_async16(base + row * ROWB + ch * 16, src, ok ? 16 : 0);
            } else {
                cp_async16(base + (BMT + row) * ROWB + ch * 16,
                           Bb + (size_t)row * K + ch * 8, 16);
            }
        }
        CP_COMMIT();
    };

    // prologue
    #pragma unroll
    for (int s = 0; s < STAGES; s++) load_stage(s, s);

    for (int t = 0; t < T; t++) {
        asm volatile("cp.async.wait_group %0;" :: "n"(STAGES - 1));
        __syncthreads();
        uint32_t Abase = sb + (uint32_t)(t % STAGES) * STAGE_BYTES;
        uint32_t Bbase = Abase + BMT * ROWB;
        const int rsel = lane & 15;

        #pragma unroll
        for (int ks = 0; ks < 2; ks++) {
            uint32_t koff = (uint32_t)(ks * 32 + (lane >> 4) * 16);
            uint32_t a[4][4], b[4][2];
            #pragma unroll
            for (int mi = 0; mi < 4; mi++)
                ldsm4(a[mi], Abase + (uint32_t)(wm + 16 * mi + rsel) * ROWB + koff);
            #pragma unroll
            for (int bj = 0; bj < 2; bj++) {
                uint32_t r[4];
                ldsm4(r, Bbase + (uint32_t)(wn + 16 * bj + rsel) * ROWB + koff);
                b[2*bj][0] = r[0]; b[2*bj][1] = r[2];
                b[2*bj+1][0] = r[1]; b[2*bj+1][1] = r[3];
            }
            #pragma unroll
            for (int mi = 0; mi < 4; mi++)
                #pragma unroll
                for (int nj = 0; nj < 4; nj++)
                    mma_f16(acc[mi][nj], a[mi], b[nj]);
        }
        __syncthreads();
        if (t + STAGES < T) load_stage(t + STAGES, t % STAGES);
        else CP_COMMIT();   // empty group keeps wait_group counting uniform
    }

    // ---- epilogue: bias / sigmoid / fp32 store / optional fp16 copy ----
    #pragma unroll
    for (int mi = 0; mi < 4; mi++) {
        #pragma unroll
        for (int half_ = 0; half_ < 2; half_++) {
            int gm = bm + wm + 16 * mi + (lane >> 2) + 8 * half_;
            if (gm >= M) continue;
            float* crow = C + (size_t)gm * Nfull;
            #pragma unroll
            for (int nj = 0; nj < 4; nj++) {
                int gn = bn + wn + 8 * nj + 2 * (lane & 3);
                float v0 = acc[mi][nj][2 * half_ + 0];
                float v1 = acc[mi][nj][2 * half_ + 1];
                if (bias) { v0 += bias[gn]; v1 += bias[gn + 1]; }
                if (act) {
                    v0 = 1.f / (1.f + __expf(-v0));
                    v1 = 1.f / (1.f + __expf(-v1));
                }
                *reinterpret_cast<float2*>(crow + gn) = make_float2(v0, v1);
                if (out16) {
                    __half2 hh; hh.x = __float2half(v0); hh.y = __float2half(v1);
                    *reinterpret_cast<__half2*>(out16 + (size_t)gm * Nfull + gn) = hh;
                }
            }
        }
    }
}

// ================= conversion kernels =================
// PAT 0 (A side): (hi, lo, hi)    PAT 1 (B side): (hi, hi, lo)
template<int PAT>
__global__ void split3_kernel(const float* __restrict__ X, __half* __restrict__ Y,
                              long total, int K)
{
    long i = blockIdx.x * (long)blockDim.x + threadIdx.x;
    if (i >= total) return;
    long m = i / K; int k = (int)(i - m * K);
    float x = X[i];
    __half hi = __float2half(x);
    __half lo = __float2half(x - __half2float(hi));
    __half* row = Y + m * (3L * K);
    if (PAT == 0) { row[k] = hi; row[K + k] = lo; row[2 * K + k] = hi; }
    else          { row[k] = hi; row[K + k] = hi; row[2 * K + k] = lo; }
}

// X: [K, N] -> Y: [N, K] plain fp16 transpose (1-term gate weights)
__global__ void split1T_kernel(const float* __restrict__ X, __half* __restrict__ Y,
                               int K, int N)
{
    int i = blockIdx.x * blockDim.x + threadIdx.x;
    if (i >= K * N) return;
    int k = i / N, n = i - k * N;
    Y[(size_t)n * K + k] = __float2half(X[i]);
}

// fused = gate_v*fi + gate_e*ti, write 3-term split (A pattern) directly
__global__ void fuse_split_kernel(const float* __restrict__ av, const float* __restrict__ fi,
                                  const float* __restrict__ ae, const float* __restrict__ ti,
                                  __half* __restrict__ Y, int n)
{
    int i = blockIdx.x * blockDim.x + threadIdx.x;
    if (i >= n) return;
    float x = av[i] * fi[i] + ae[i] * ti[i];
    int m = i >> 9, k = i & 511;
    __half hi = __float2half(x);
    __half lo = __float2half(x - __half2float(hi));
    __half* row = Y + (size_t)m * 1536;
    row[k] = hi; row[512 + k] = lo; row[1024 + k] = hi;
}

// h3 = split(elu(hbuf))
__global__ void elu_split_kernel(const float* __restrict__ H, __half* __restrict__ Y, int n)
{
    int i = blockIdx.x * blockDim.x + threadIdx.x;
    if (i >= n) return;
    float x = H[i];
    x = x > 0.f ? x : expm1f(x);
    int m = i >> 9, k = i & 511;
    __half hi = __float2half(x);
    __half lo = __float2half(x - __half2float(hi));
    __half* row = Y + (size_t)m * 1536;
    row[k] = hi; row[512 + k] = lo; row[1024 + k] = hi;
}

// ================= misc elementwise =================
__global__ void fill_kernel(float* __restrict__ p, float v, int n) {
    int i = blockIdx.x * blockDim.x + threadIdx.x;
    if (i < n) p[i] = v;
}

// ================= GAT score / softmax / aggregation =================
// Warp-collective: one warp per (node, head). Coalesced float2 loads + shfl reduce.
__global__ void scores_warp_kernel(const float* __restrict__ z, const float* __restrict__ a,
                                   float* __restrict__ ssrc, float* __restrict__ sdst,
                                   int Nn, int H, int O)
{
    int gw = (blockIdx.x * blockDim.x + threadIdx.x) >> 5;
    int lane = threadIdx.x & 31;
    if (gw >= Nn * H) return;
    int n = gw / H, h = gw - n * H;
    const float2* zp = reinterpret_cast<const float2*>(z + ((size_t)n * H + h) * O);
    const float2* as = reinterpret_cast<const float2*>(a + (size_t)h * 2 * O);
    const float2* ad = reinterpret_cast<const float2*>(a + (size_t)h * 2 * O + O);
    float s1 = 0.f, s2 = 0.f;
    for (int o = lane; o < (O >> 1); o += 32) {
        float2 zv = zp[o];
        float2 a1 = as[o], a2 = ad[o];
        s1 = fmaf(zv.x, a1.x, fmaf(zv.y, a1.y, s1));
        s2 = fmaf(zv.x, a2.x, fmaf(zv.y, a2.y, s2));
    }
    #pragma unroll
    for (int off = 16; off > 0; off >>= 1) {
        s1 += __shfl_xor_sync(0xFFFFFFFF, s1, off);
        s2 += __shfl_xor_sync(0xFFFFFFFF, s2, off);
    }
    if (lane == 0) { ssrc[gw] = s1; sdst[gw] = s2; }
}

// Single-pass softmax numerator + denominator (no max shift: logits are O(10),
// exp is safely finite in fp32; identical math to the shifted reference).
__global__ void edge_soft_kernel(const float* __restrict__ ssrc, const float* __restrict__ sdst,
                                 const int* __restrict__ src, const int* __restrict__ dst,
                                 float* __restrict__ ebuf, float* __restrict__ den,
                                 int E, int H)
{
    int idx = blockIdx.x * blockDim.x + threadIdx.x;
    if (idx >= E * H) return;
    int e = idx / H, h = idx - e * H;
    int s = src[e], d = dst[e];
    float v = ssrc[(size_t)s * H + h] + sdst[(size_t)d * H + h];
    v = v > 0.f ? v : 0.01f * v;           // leaky_relu(0.01)
    float ex = __expf(v);
    ebuf[idx] = ex;
    asm volatile("red.global.add.f32 [%0], %1;"
                 :: "l"(den + (size_t)d * H + h), "f"(ex) : "memory");
}

__global__ void edge_agg_kernel(const float* __restrict__ ex, const float* __restrict__ den,
                                const int* __restrict__ src, const int* __restrict__ dst,
                                const float* __restrict__ z, float* __restrict__ out,
                                int E, int H, int O)
{
    int idx = blockIdx.x * blockDim.x + threadIdx.x;
    int groups = O / 4;
    int per_edge = H * groups;
    if (idx >= E * per_edge) return;
    int e = idx / per_edge;
    int r = idx % per_edge;
    int h = r / groups;
    int q = r % groups;
    int s = src[e], d = dst[e];
    float coef = ex[(size_t)e * H + h] / den[(size_t)d * H + h];
    const float4 zv = *reinterpret_cast<const float4*>(z + ((size_t)s * H + h) * O + q * 4);
    float* po = out + ((size_t)d * H + h) * O + q * 4;
    asm volatile("red.global.add.v4.f32 [%0], {%1, %2, %3, %4};"
                 :: "l"(po), "f"(coef * zv.x), "f"(coef * zv.y),
                    "f"(coef * zv.z), "f"(coef * zv.w) : "memory");
}

// ================= host orchestration =================
static inline int cdiv(int a, int b) { return (a + b - 1) / b; }

static void launch_gemm(const __half* A, const __half* B, float* C,
                        const float* bias, int act, __half* out16,
                        int M, int Nfull, int K)
{
    static int smem_set = 0;
    const int smem = STAGES * STAGE_BYTES;   // 61440
    if (!smem_set) {
        cudaFuncSetAttribute(gemm_f16_kernel,
                             cudaFuncAttributeMaxDynamicSharedMemorySize, smem);
        smem_set = 1;
    }
    dim3 grid(Nfull / BNT, cdiv(M, BMT));
    gemm_f16_kernel<<<grid, 256, smem>>>(A, B, C, bias, act, out16, M, Nfull, K);
}

extern "C" void kernel_launch(void* const* d_in, const int* in_sizes, int n_in,
                              void* d_out, int out_size)
{
    const float* img   = (const float*)d_in[0];
    const float* blk   = (const float*)d_in[1];
    const float* W_img = (const float*)d_in[2];
    const float* W_blk = (const float*)d_in[3];
    const float* Wv    = (const float*)d_in[4];
    const float* bv    = (const float*)d_in[5];
    const float* We    = (const float*)d_in[6];
    const float* be    = (const float*)d_in[7];
    const float* fc1   = (const float*)d_in[8];
    const float* attn1 = (const float*)d_in[9];
    const float* fc2   = (const float*)d_in[10];
    const float* attn2 = (const float*)d_in[11];
    const int* e0s = (const int*)d_in[12];
    const int* e0d = (const int*)d_in[13];
    const int* e1s = (const int*)d_in[14];
    const int* e1d = (const int*)d_in[15];
    float* out = (float*)d_out;

    int E0 = in_sizes[12];
    int E1 = in_sizes[14];

    float *fi, *ti, *av, *ae, *hbuf, *z2;
    float *s1s, *s1d, *e1b, *d1, *s2s, *s2d, *e2b, *d2;
    __half *img3, *blk3, *fi1, *ti1, *fu3, *h3;
    __half *wimg3, *wblk3, *wv1, *we1, *fc13, *fc23;
    cudaGetSymbolAddress((void**)&fi,  g_fi);
    cudaGetSymbolAddress((void**)&ti,  g_ti);
    cudaGetSymbolAddress((void**)&av,  g_av);
    cudaGetSymbolAddress((void**)&ae,  g_ae);
    cudaGetSymbolAddress((void**)&hbuf,g_h);
    cudaGetSymbolAddress((void**)&z2,  g_z2);
    cudaGetSymbolAddress((void**)&s1s, g_s1s);
    cudaGetSymbolAddress((void**)&s1d, g_s1d);
    cudaGetSymbolAddress((void**)&e1b, g_e1);
    cudaGetSymbolAddress((void**)&d1,  g_d1);
    cudaGetSymbolAddress((void**)&s2s, g_s2s);
    cudaGetSymbolAddress((void**)&s2d, g_s2d);
    cudaGetSymbolAddress((void**)&e2b, g_e2);
    cudaGetSymbolAddress((void**)&d2,  g_d2);
    cudaGetSymbolAddress((void**)&img3, g_img3);
    cudaGetSymbolAddress((void**)&blk3, g_blk3);
    cudaGetSymbolAddress((void**)&fi1,  g_fi1);
    cudaGetSymbolAddress((void**)&ti1,  g_ti1);
    cudaGetSymbolAddress((void**)&fu3,  g_fu3);
    cudaGetSymbolAddress((void**)&h3,   g_h3);
    cudaGetSymbolAddress((void**)&wimg3, g_wimg3);
    cudaGetSymbolAddress((void**)&wblk3, g_wblk3);
    cudaGetSymbolAddress((void**)&wv1,   g_wv1);
    cudaGetSymbolAddress((void**)&we1,   g_we1);
    cudaGetSymbolAddress((void**)&fc13,  g_fc13);
    cudaGetSymbolAddress((void**)&fc23,  g_fc23);

    // --- init accumulators / outputs ---
    {
        int n;
        n = NDST0 * FUSED_D; fill_kernel<<<cdiv(n,256),256>>>(hbuf, 0.f, n);
        n = NDST1 * O2;      fill_kernel<<<cdiv(n,256),256>>>(out,  0.f, n);
        n = NDST0 * H1;      fill_kernel<<<cdiv(n,256),256>>>(d1, 0.f, n);
        n = NDST1;           fill_kernel<<<cdiv(n,256),256>>>(d2, 0.f, n);
    }

    // --- weight conversions (small) ---
    split3_kernel<1><<<cdiv(512*IMG_D,256),256>>>(W_img, wimg3, (long)512*IMG_D, IMG_D);
    split3_kernel<1><<<cdiv(512*BLK_D,256),256>>>(W_blk, wblk3, (long)512*BLK_D, BLK_D);
    split1T_kernel<<<cdiv(512*512,256),256>>>(Wv, wv1, 512, 512);
    split1T_kernel<<<cdiv(512*512,256),256>>>(We, we1, 512, 512);
    split3_kernel<1><<<cdiv(512*512,256),256>>>(fc1, fc13, (long)512*512, 512);
    split3_kernel<1><<<cdiv(128*512,256),256>>>(fc2, fc23, (long)128*512, 512);

    // --- input conversions ---
    {
        long n = (long)NSRC0 * IMG_D;
        split3_kernel<0><<<(int)((n + 255) / 256), 256>>>(img, img3, n, IMG_D);
    }
    {
        long n = (long)NSRC0 * BLK_D;
        split3_kernel<0><<<(int)((n + 255) / 256), 256>>>(blk, blk3, n, BLK_D);
    }

    // --- CrossAttentionLayer ---
    // fi = img @ W_img^T  (3-term, K=3072) + fp16 copy for gate GEMM
    launch_gemm(img3, wimg3, fi, nullptr, 0, fi1, NSRC0, FUSED_D, 3*IMG_D);
    // ti = blk @ W_blk^T  (3-term, K=2304)
    launch_gemm(blk3, wblk3, ti, nullptr, 0, ti1, NSRC0, FUSED_D, 3*BLK_D);
    // av = sigmoid(fi @ Wv + bv)   -- 1-term fp16, K=512
    launch_gemm(fi1, wv1, av, bv, 1, nullptr, NSRC0, FUSED_D, FUSED_D);
    // ae = sigmoid(ti @ We + be)   -- 1-term fp16, K=512
    launch_gemm(ti1, we1, ae, be, 1, nullptr, NSRC0, FUSED_D, FUSED_D);
    {
        int n = NSRC0 * FUSED_D;
        fuse_split_kernel<<<cdiv(n,256),256>>>(av, fi, ae, ti, fu3, n);
    }

    // --- Layer 1: 8-head GAT ---
    launch_gemm(fu3, fc13, fi, nullptr, 0, nullptr, NSRC0, FUSED_D, 3*FUSED_D);
    {
        int nw = NSRC0 * H1;                       // one warp per (node, head)
        scores_warp_kernel<<<cdiv(nw * 32, 256), 256>>>(fi, attn1, s1s, s1d, NSRC0, H1, O1);
    }
    {
        int n = E0 * H1;
        edge_soft_kernel<<<cdiv(n,256),256>>>(s1s, s1d, e0s, e0d, e1b, d1, E0, H1);
        int na = E0 * H1 * (O1/4);
        edge_agg_kernel<<<cdiv(na,256),256>>>(e1b, d1, e0s, e0d, fi, hbuf, E0, H1, O1);
    }
    {
        int n = NDST0 * FUSED_D;
        elu_split_kernel<<<cdiv(n,256),256>>>(hbuf, h3, n);
    }

    // --- Layer 2: 1-head GAT ---
    launch_gemm(h3, fc23, z2, nullptr, 0, nullptr, NDST0, O2, 3*FUSED_D);
    {
        int nw = NDST0;
        scores_warp_kernel<<<cdiv(nw * 32, 256), 256>>>(z2, attn2, s2s, s2d, NDST0, 1, O2);
    }
    {
        int n = E1;
        edge_soft_kernel<<<cdiv(n,256),256>>>(s2s, s2d, e1s, e1d, e2b, d2, E1, 1);
        int na = E1 * (O2/4);
        edge_agg_kernel<<<cdiv(na,256),256>>>(e2b, d2, e1s, e1d, z2, out, E1, 1, O2);
    }

    (void)n_in; (void)out_size; (void)in_sizes;
}

// round 17
// speedup vs baseline: 3.1119x; 1.1433x over previous
#include <cuda_runtime.h>
#include <cuda_fp16.h>
#include <math.h>
#include <stdint.h>

// ---------------- Problem constants ----------------
#define NSRC0   60000
#define NDST0   30000
#define NE0     480000
#define NDST1   8000
#define NE1     128000
#define IMG_D   1024
#define BLK_D   768
#define FUSED_D 512
#define H1      8
#define O1      64
#define O2      128

// ---------------- fp32 scratch ----------------
__device__ float g_fi[(size_t)NSRC0 * FUSED_D];   // fi, later z1
__device__ float g_ti[(size_t)NSRC0 * FUSED_D];
__device__ float g_av[(size_t)NSRC0 * FUSED_D];
__device__ float g_ae[(size_t)NSRC0 * FUSED_D];
__device__ float g_h [(size_t)NDST0 * FUSED_D];
__device__ float g_z2[(size_t)NDST0 * O2];
__device__ float g_s1s[(size_t)NSRC0 * H1];
__device__ float g_s1d[(size_t)NSRC0 * H1];
__device__ float g_e1 [(size_t)NE0   * H1];
__device__ float g_d1 [(size_t)NDST0 * H1];
__device__ float g_s2s[(size_t)NDST0];
__device__ float g_s2d[(size_t)NDST0];
__device__ float g_e2 [(size_t)NE1];
__device__ float g_d2 [(size_t)NDST1];

// ---------------- fp16 split scratch ----------------
__device__ __half g_img2[(size_t)NSRC0 * 2 * IMG_D];   // A 2-term (hi,lo)
__device__ __half g_blk2[(size_t)NSRC0 * 2 * BLK_D];
__device__ __half g_fi1 [(size_t)NSRC0 * FUSED_D];     // 1-term fp16 fi (gate input)
__device__ __half g_ti1 [(size_t)NSRC0 * FUSED_D];
__device__ __half g_fu3 [(size_t)NSRC0 * 3 * FUSED_D];
__device__ __half g_h3  [(size_t)NDST0 * 3 * FUSED_D];
__device__ __half g_wimg2[512 * 2 * IMG_D];            // B 2-term (hi,hi)
__device__ __half g_wblk2[512 * 2 * BLK_D];
__device__ __half g_wv1  [512 * FUSED_D];              // 1-term fp16 Wv^T
__device__ __half g_we1  [512 * FUSED_D];
__device__ __half g_fc13 [512 * 3 * FUSED_D];
__device__ __half g_fc23 [128 * 3 * FUSED_D];

// ================= PTX helpers (family-profile-safe only) =================
__device__ __forceinline__ uint32_t smem_u32(const void* p) {
    return (uint32_t)__cvta_generic_to_shared(p);
}

__device__ __forceinline__ void cp_async16(uint32_t dst, const void* src, int sz) {
    asm volatile("cp.async.cg.shared.global [%0], [%1], 16, %2;"
                 :: "r"(dst), "l"(src), "r"(sz));
}
#define CP_COMMIT() asm volatile("cp.async.commit_group;" ::: "memory")

__device__ __forceinline__ void ldsm4(uint32_t* r, uint32_t addr) {
    asm volatile("ldmatrix.sync.aligned.m8n8.x4.shared.b16 {%0,%1,%2,%3}, [%4];"
                 : "=r"(r[0]), "=r"(r[1]), "=r"(r[2]), "=r"(r[3]) : "r"(addr));
}

__device__ __forceinline__ void mma_f16(float* c, const uint32_t* a, const uint32_t* b) {
    asm volatile(
        "mma.sync.aligned.m16n8k16.row.col.f32.f16.f16.f32 "
        "{%0,%1,%2,%3}, {%4,%5,%6,%7}, {%8,%9}, {%0,%1,%2,%3};"
        : "+f"(c[0]), "+f"(c[1]), "+f"(c[2]), "+f"(c[3])
        : "r"(a[0]), "r"(a[1]), "r"(a[2]), "r"(a[3]), "r"(b[0]), "r"(b[1]));
}

// ================= fp16 HMMA GEMM =================
// C[M,Nfull] = A[M,K] * B[Nfull,K]^T  (fp16 K-major rows), fp32 accumulate.
// Tile 128x128xBK32, 3-stage cp.async pipeline, 8 warps @ 64x32, 2 CTAs/SM.
#define BMT 128
#define BNT 128
#define BKT 32
#define STAGES 3
#define ROWB 80                 // 32 halves + 8 pad halves = 80 bytes/row
#define STAGE_BYTES ((BMT + BNT) * ROWB)   // 20480

__global__ void __launch_bounds__(256, 2)
gemm_f16_kernel(const __half* __restrict__ A,
                const __half* __restrict__ B,
                float* __restrict__ C,
                const float* __restrict__ bias, int act,
                __half* __restrict__ out16,
                int M, int Nfull, int K)
{
    extern __shared__ char smem[];
    const int tid = threadIdx.x;
    const int lane = tid & 31, wid = tid >> 5;
    const int bm = blockIdx.y * BMT;
    const int bn = blockIdx.x * BNT;
    const int wm = (wid >> 2) * 64;      // 2 warp-rows
    const int wn = (wid & 3) * 32;       // 4 warp-cols
    const int T = K / BKT;
    const uint32_t sb = smem_u32(smem);

    float acc[4][4][4];
    #pragma unroll
    for (int i = 0; i < 4; i++)
        #pragma unroll
        for (int j = 0; j < 4; j++)
            #pragma unroll
            for (int k = 0; k < 4; k++) acc[i][j][k] = 0.f;

    // ---- stage loader: A rows then B rows, 16B chunks ----
    auto load_stage = [&](int t, int s) {
        uint32_t base = sb + (uint32_t)s * STAGE_BYTES;
        const __half* Ab = A + (size_t)bm * K + (size_t)t * BKT;
        const __half* Bb = B + (size_t)bn * K + (size_t)t * BKT;
        #pragma unroll
        for (int i = tid; i < 1024; i += 256) {
            int row = (i >> 2) & 127;
            int ch  = i & 3;
            if (i < 512) {
                int ok = (bm + row < M);
                const __half* src = Ab + (size_t)(ok ? row : 0) * K + ch * 8;
                cp_async16(base + row * ROWB + ch * 16, src, ok ? 16 : 0);
            } else {
                cp_async16(base + (BMT + row) * ROWB + ch * 16,
                           Bb + (size_t)row * K + ch * 8, 16);
            }
        }
        CP_COMMIT();
    };

    // prologue
    #pragma unroll
    for (int s = 0; s < STAGES; s++) load_stage(s, s);

    for (int t = 0; t < T; t++) {
        asm volatile("cp.async.wait_group %0;" :: "n"(STAGES - 1));
        __syncthreads();
        uint32_t Abase = sb + (uint32_t)(t % STAGES) * STAGE_BYTES;
        uint32_t Bbase = Abase + BMT * ROWB;
        const int rsel = lane & 15;

        #pragma unroll
        for (int ks = 0; ks < 2; ks++) {
            uint32_t koff = (uint32_t)(ks * 32 + (lane >> 4) * 16);
            uint32_t a[4][4], b[4][2];
            #pragma unroll
            for (int mi = 0; mi < 4; mi++)
                ldsm4(a[mi], Abase + (uint32_t)(wm + 16 * mi + rsel) * ROWB + koff);
            #pragma unroll
            for (int bj = 0; bj < 2; bj++) {
                uint32_t r[4];
                ldsm4(r, Bbase + (uint32_t)(wn + 16 * bj + rsel) * ROWB + koff);
                b[2*bj][0] = r[0]; b[2*bj][1] = r[2];
                b[2*bj+1][0] = r[1]; b[2*bj+1][1] = r[3];
            }
            #pragma unroll
            for (int mi = 0; mi < 4; mi++)
                #pragma unroll
                for (int nj = 0; nj < 4; nj++)
                    mma_f16(acc[mi][nj], a[mi], b[nj]);
        }
        __syncthreads();
        if (t + STAGES < T) load_stage(t + STAGES, t % STAGES);
        else CP_COMMIT();   // empty group keeps wait_group counting uniform
    }

    // ---- epilogue: bias / sigmoid / fp32 store / optional fp16 copy ----
    #pragma unroll
    for (int mi = 0; mi < 4; mi++) {
        #pragma unroll
        for (int half_ = 0; half_ < 2; half_++) {
            int gm = bm + wm + 16 * mi + (lane >> 2) + 8 * half_;
            if (gm >= M) continue;
            float* crow = C + (size_t)gm * Nfull;
            #pragma unroll
            for (int nj = 0; nj < 4; nj++) {
                int gn = bn + wn + 8 * nj + 2 * (lane & 3);
                float v0 = acc[mi][nj][2 * half_ + 0];
                float v1 = acc[mi][nj][2 * half_ + 1];
                if (bias) { v0 += bias[gn]; v1 += bias[gn + 1]; }
                if (act) {
                    v0 = 1.f / (1.f + __expf(-v0));
                    v1 = 1.f / (1.f + __expf(-v1));
                }
                *reinterpret_cast<float2*>(crow + gn) = make_float2(v0, v1);
                if (out16) {
                    __half2 hh; hh.x = __float2half(v0); hh.y = __float2half(v1);
                    *reinterpret_cast<__half2*>(out16 + (size_t)gm * Nfull + gn) = hh;
                }
            }
        }
    }
}

// ================= conversion kernels =================
// 2-term: PAT 0 (A side): (hi, lo)    PAT 1 (B side): (hi, hi)
template<int PAT>
__global__ void split2_kernel(const float* __restrict__ X, __half* __restrict__ Y,
                              long total, int K)
{
    long i = blockIdx.x * (long)blockDim.x + threadIdx.x;
    if (i >= total) return;
    long m = i / K; int k = (int)(i - m * K);
    float x = X[i];
    __half hi = __float2half(x);
    __half* row = Y + m * (2L * K);
    if (PAT == 0) {
        __half lo = __float2half(x - __half2float(hi));
        row[k] = hi; row[K + k] = lo;
    } else {
        row[k] = hi; row[K + k] = hi;
    }
}

// 3-term: PAT 0 (A side): (hi, lo, hi)    PAT 1 (B side): (hi, hi, lo)
template<int PAT>
__global__ void split3_kernel(const float* __restrict__ X, __half* __restrict__ Y,
                              long total, int K)
{
    long i = blockIdx.x * (long)blockDim.x + threadIdx.x;
    if (i >= total) return;
    long m = i / K; int k = (int)(i - m * K);
    float x = X[i];
    __half hi = __float2half(x);
    __half lo = __float2half(x - __half2float(hi));
    __half* row = Y + m * (3L * K);
    if (PAT == 0) { row[k] = hi; row[K + k] = lo; row[2 * K + k] = hi; }
    else          { row[k] = hi; row[K + k] = hi; row[2 * K + k] = lo; }
}

// X: [K, N] -> Y: [N, K] plain fp16 transpose (1-term gate weights)
__global__ void split1T_kernel(const float* __restrict__ X, __half* __restrict__ Y,
                               int K, int N)
{
    int i = blockIdx.x * blockDim.x + threadIdx.x;
    if (i >= K * N) return;
    int k = i / N, n = i - k * N;
    Y[(size_t)n * K + k] = __float2half(X[i]);
}

// fused = gate_v*fi + gate_e*ti, write 3-term split (A pattern) directly
__global__ void fuse_split_kernel(const float* __restrict__ av, const float* __restrict__ fi,
                                  const float* __restrict__ ae, const float* __restrict__ ti,
                                  __half* __restrict__ Y, int n)
{
    int i = blockIdx.x * blockDim.x + threadIdx.x;
    if (i >= n) return;
    float x = av[i] * fi[i] + ae[i] * ti[i];
    int m = i >> 9, k = i & 511;
    __half hi = __float2half(x);
    __half lo = __float2half(x - __half2float(hi));
    __half* row = Y + (size_t)m * 1536;
    row[k] = hi; row[512 + k] = lo; row[1024 + k] = hi;
}

// h3 = split(elu(hbuf))
__global__ void elu_split_kernel(const float* __restrict__ H, __half* __restrict__ Y, int n)
{
    int i = blockIdx.x * blockDim.x + threadIdx.x;
    if (i >= n) return;
    float x = H[i];
    x = x > 0.f ? x : expm1f(x);
    int m = i >> 9, k = i & 511;
    __half hi = __float2half(x);
    __half lo = __float2half(x - __half2float(hi));
    __half* row = Y + (size_t)m * 1536;
    row[k] = hi; row[512 + k] = lo; row[1024 + k] = hi;
}

// ================= misc elementwise =================
__global__ void fill_kernel(float* __restrict__ p, float v, int n) {
    int i = blockIdx.x * blockDim.x + threadIdx.x;
    if (i < n) p[i] = v;
}

// ================= GAT score / softmax / aggregation =================
// Warp-collective: one warp per (node, head). Coalesced float2 loads + shfl reduce.
__global__ void scores_warp_kernel(const float* __restrict__ z, const float* __restrict__ a,
                                   float* __restrict__ ssrc, float* __restrict__ sdst,
                                   int Nn, int H, int O)
{
    int gw = (blockIdx.x * blockDim.x + threadIdx.x) >> 5;
    int lane = threadIdx.x & 31;
    if (gw >= Nn * H) return;
    int n = gw / H, h = gw - n * H;
    const float2* zp = reinterpret_cast<const float2*>(z + ((size_t)n * H + h) * O);
    const float2* as = reinterpret_cast<const float2*>(a + (size_t)h * 2 * O);
    const float2* ad = reinterpret_cast<const float2*>(a + (size_t)h * 2 * O + O);
    float s1 = 0.f, s2 = 0.f;
    for (int o = lane; o < (O >> 1); o += 32) {
        float2 zv = zp[o];
        float2 a1 = as[o], a2 = ad[o];
        s1 = fmaf(zv.x, a1.x, fmaf(zv.y, a1.y, s1));
        s2 = fmaf(zv.x, a2.x, fmaf(zv.y, a2.y, s2));
    }
    #pragma unroll
    for (int off = 16; off > 0; off >>= 1) {
        s1 += __shfl_xor_sync(0xFFFFFFFF, s1, off);
        s2 += __shfl_xor_sync(0xFFFFFFFF, s2, off);
    }
    if (lane == 0) { ssrc[gw] = s1; sdst[gw] = s2; }
}

// Single-pass softmax numerator + denominator (no max shift: logits are O(10),
// exp is safely finite in fp32; identical math to the shifted reference).
__global__ void edge_soft_kernel(const float* __restrict__ ssrc, const float* __restrict__ sdst,
                                 const int* __restrict__ src, const int* __restrict__ dst,
                                 float* __restrict__ ebuf, float* __restrict__ den,
                                 int E, int H)
{
    int idx = blockIdx.x * blockDim.x + threadIdx.x;
    if (idx >= E * H) return;
    int e = idx / H, h = idx - e * H;
    int s = src[e], d = dst[e];
    float v = ssrc[(size_t)s * H + h] + sdst[(size_t)d * H + h];
    v = v > 0.f ? v : 0.01f * v;           // leaky_relu(0.01)
    float ex = __expf(v);
    ebuf[idx] = ex;
    asm volatile("red.global.add.f32 [%0], %1;"
                 :: "l"(den + (size_t)d * H + h), "f"(ex) : "memory");
}

__global__ void edge_agg_kernel(const float* __restrict__ ex, const float* __restrict__ den,
                                const int* __restrict__ src, const int* __restrict__ dst,
                                const float* __restrict__ z, float* __restrict__ out,
                                int E, int H, int O)
{
    int idx = blockIdx.x * blockDim.x + threadIdx.x;
    int groups = O / 4;
    int per_edge = H * groups;
    if (idx >= E * per_edge) return;
    int e = idx / per_edge;
    int r = idx % per_edge;
    int h = r / groups;
    int q = r % groups;
    int s = src[e], d = dst[e];
    float coef = ex[(size_t)e * H + h] / den[(size_t)d * H + h];
    const float4 zv = *reinterpret_cast<const float4*>(z + ((size_t)s * H + h) * O + q * 4);
    float* po = out + ((size_t)d * H + h) * O + q * 4;
    asm volatile("red.global.add.v4.f32 [%0], {%1, %2, %3, %4};"
                 :: "l"(po), "f"(coef * zv.x), "f"(coef * zv.y),
                    "f"(coef * zv.z), "f"(coef * zv.w) : "memory");
}

// ================= host orchestration =================
static inline int cdiv(int a, int b) { return (a + b - 1) / b; }

static void launch_gemm(const __half* A, const __half* B, float* C,
                        const float* bias, int act, __half* out16,
                        int M, int Nfull, int K)
{
    static int smem_set = 0;
    const int smem = STAGES * STAGE_BYTES;   // 61440
    if (!smem_set) {
        cudaFuncSetAttribute(gemm_f16_kernel,
                             cudaFuncAttributeMaxDynamicSharedMemorySize, smem);
        smem_set = 1;
    }
    dim3 grid(Nfull / BNT, cdiv(M, BMT));
    gemm_f16_kernel<<<grid, 256, smem>>>(A, B, C, bias, act, out16, M, Nfull, K);
}

extern "C" void kernel_launch(void* const* d_in, const int* in_sizes, int n_in,
                              void* d_out, int out_size)
{
    const float* img   = (const float*)d_in[0];
    const float* blk   = (const float*)d_in[1];
    const float* W_img = (const float*)d_in[2];
    const float* W_blk = (const float*)d_in[3];
    const float* Wv    = (const float*)d_in[4];
    const float* bv    = (const float*)d_in[5];
    const float* We    = (const float*)d_in[6];
    const float* be    = (const float*)d_in[7];
    const float* fc1   = (const float*)d_in[8];
    const float* attn1 = (const float*)d_in[9];
    const float* fc2   = (const float*)d_in[10];
    const float* attn2 = (const float*)d_in[11];
    const int* e0s = (const int*)d_in[12];
    const int* e0d = (const int*)d_in[13];
    const int* e1s = (const int*)d_in[14];
    const int* e1d = (const int*)d_in[15];
    float* out = (float*)d_out;

    int E0 = in_sizes[12];
    int E1 = in_sizes[14];

    float *fi, *ti, *av, *ae, *hbuf, *z2;
    float *s1s, *s1d, *e1b, *d1, *s2s, *s2d, *e2b, *d2;
    __half *img2, *blk2, *fi1, *ti1, *fu3, *h3;
    __half *wimg2, *wblk2, *wv1, *we1, *fc13, *fc23;
    cudaGetSymbolAddress((void**)&fi,  g_fi);
    cudaGetSymbolAddress((void**)&ti,  g_ti);
    cudaGetSymbolAddress((void**)&av,  g_av);
    cudaGetSymbolAddress((void**)&ae,  g_ae);
    cudaGetSymbolAddress((void**)&hbuf,g_h);
    cudaGetSymbolAddress((void**)&z2,  g_z2);
    cudaGetSymbolAddress((void**)&s1s, g_s1s);
    cudaGetSymbolAddress((void**)&s1d, g_s1d);
    cudaGetSymbolAddress((void**)&e1b, g_e1);
    cudaGetSymbolAddress((void**)&d1,  g_d1);
    cudaGetSymbolAddress((void**)&s2s, g_s2s);
    cudaGetSymbolAddress((void**)&s2d, g_s2d);
    cudaGetSymbolAddress((void**)&e2b, g_e2);
    cudaGetSymbolAddress((void**)&d2,  g_d2);
    cudaGetSymbolAddress((void**)&img2, g_img2);
    cudaGetSymbolAddress((void**)&blk2, g_blk2);
    cudaGetSymbolAddress((void**)&fi1,  g_fi1);
    cudaGetSymbolAddress((void**)&ti1,  g_ti1);
    cudaGetSymbolAddress((void**)&fu3,  g_fu3);
    cudaGetSymbolAddress((void**)&h3,   g_h3);
    cudaGetSymbolAddress((void**)&wimg2, g_wimg2);
    cudaGetSymbolAddress((void**)&wblk2, g_wblk2);
    cudaGetSymbolAddress((void**)&wv1,   g_wv1);
    cudaGetSymbolAddress((void**)&we1,   g_we1);
    cudaGetSymbolAddress((void**)&fc13,  g_fc13);
    cudaGetSymbolAddress((void**)&fc23,  g_fc23);

    // --- init accumulators / outputs ---
    {
        int n;
        n = NDST0 * FUSED_D; fill_kernel<<<cdiv(n,256),256>>>(hbuf, 0.f, n);
        n = NDST1 * O2;      fill_kernel<<<cdiv(n,256),256>>>(out,  0.f, n);
        n = NDST0 * H1;      fill_kernel<<<cdiv(n,256),256>>>(d1, 0.f, n);
        n = NDST1;           fill_kernel<<<cdiv(n,256),256>>>(d2, 0.f, n);
    }

    // --- weight conversions (small) ---
    split2_kernel<1><<<cdiv(512*IMG_D,256),256>>>(W_img, wimg2, (long)512*IMG_D, IMG_D);
    split2_kernel<1><<<cdiv(512*BLK_D,256),256>>>(W_blk, wblk2, (long)512*BLK_D, BLK_D);
    split1T_kernel<<<cdiv(512*512,256),256>>>(Wv, wv1, 512, 512);
    split1T_kernel<<<cdiv(512*512,256),256>>>(We, we1, 512, 512);
    split3_kernel<1><<<cdiv(512*512,256),256>>>(fc1, fc13, (long)512*512, 512);
    split3_kernel<1><<<cdiv(128*512,256),256>>>(fc2, fc23, (long)128*512, 512);

    // --- input conversions (2-term) ---
    {
        long n = (long)NSRC0 * IMG_D;
        split2_kernel<0><<<(int)((n + 255) / 256), 256>>>(img, img2, n, IMG_D);
    }
    {
        long n = (long)NSRC0 * BLK_D;
        split2_kernel<0><<<(int)((n + 255) / 256), 256>>>(blk, blk2, n, BLK_D);
    }

    // --- CrossAttentionLayer ---
    // fi = img @ W_img^T  (2-term, K=2048) + fp16 copy for gate GEMM
    launch_gemm(img2, wimg2, fi, nullptr, 0, fi1, NSRC0, FUSED_D, 2*IMG_D);
    // ti = blk @ W_blk^T  (2-term, K=1536)
    launch_gemm(blk2, wblk2, ti, nullptr, 0, ti1, NSRC0, FUSED_D, 2*BLK_D);
    // av = sigmoid(fi @ Wv + bv)   -- 1-term fp16, K=512
    launch_gemm(fi1, wv1, av, bv, 1, nullptr, NSRC0, FUSED_D, FUSED_D);
    // ae = sigmoid(ti @ We + be)   -- 1-term fp16, K=512
    launch_gemm(ti1, we1, ae, be, 1, nullptr, NSRC0, FUSED_D, FUSED_D);
    {
        int n = NSRC0 * FUSED_D;
        fuse_split_kernel<<<cdiv(n,256),256>>>(av, fi, ae, ti, fu3, n);
    }

    // --- Layer 1: 8-head GAT ---
    launch_gemm(fu3, fc13, fi, nullptr, 0, nullptr, NSRC0, FUSED_D, 3*FUSED_D);
    {
        int nw = NSRC0 * H1;                       // one warp per (node, head)
        scores_warp_kernel<<<cdiv(nw * 32, 256), 256>>>(fi, attn1, s1s, s1d, NSRC0, H1, O1);
    }
    {
        int n = E0 * H1;
        edge_soft_kernel<<<cdiv(n,256),256>>>(s1s, s1d, e0s, e0d, e1b, d1, E0, H1);
        int na = E0 * H1 * (O1/4);
        edge_agg_kernel<<<cdiv(na,256),256>>>(e1b, d1, e0s, e0d, fi, hbuf, E0, H1, O1);
    }
    {
        int n = NDST0 * FUSED_D;
        elu_split_kernel<<<cdiv(n,256),256>>>(hbuf, h3, n);
    }

    // --- Layer 2: 1-head GAT ---
    launch_gemm(h3, fc23, z2, nullptr, 0, nullptr, NDST0, O2, 3*FUSED_D);
    {
        int nw = NDST0;
        scores_warp_kernel<<<cdiv(nw * 32, 256), 256>>>(z2, attn2, s2s, s2d, NDST0, 1, O2);
    }
    {
        int n = E1;
        edge_soft_kernel<<<cdiv(n,256),256>>>(s2s, s2d, e1s, e1d, e2b, d2, E1, 1);
        int na = E1 * (O2/4);
        edge_agg_kernel<<<cdiv(na,256),256>>>(e2b, d2, e1s, e1d, z2, out, E1, 1, O2);
    }

    (void)n_in; (void)out_size; (void)in_sizes;
}